// round 2
// baseline (speedup 1.0000x reference)
#include <cuda_runtime.h>
#include <math.h>

// Problem constants
#define B_  8
#define N_  2048
#define M_  2048
#define D_  512
#define H_  8
#define BH_ (B_ * H_)
#define HD_ (H_ * D_)

// -------------------------------------------------------------------------
// Device scratch (static __device__ arrays — allocation-free per harness rules)
// -------------------------------------------------------------------------
__device__ float g_kp[(size_t)BH_ * N_ * D_];      // 256 MB  k' [B,H,N,D]
__device__ float g_vp[(size_t)BH_ * N_ * D_];      // 256 MB  v' [B,H,N,D]
__device__ float g_qp[(size_t)BH_ * M_ * D_];      // 256 MB  q' [B,H,M,D]
__device__ float g_scores[(size_t)BH_ * M_ * N_];  // 1 GiB   scores [B,H,M,N]
__device__ float g_attn[(size_t)BH_ * M_ * D_];    // 256 MB  attn out [B,H,M,D]
__device__ float g_outs[(size_t)B_ * M_ * HD_];    // 256 MB  interleaved [B,M,D*H]

// -------------------------------------------------------------------------
// Batched SGEMM: C[z] = alpha * A[z] @ B[z] (+ bias), 128x128x8 tiles,
// 8x8 per-thread microtile, 256 threads. All dims must be multiples of the
// tile (true for every GEMM in this pipeline: M,N in {512,2048}, K in
// {512,2048,4096}).
//
// Batch addressing: A += (z / divA) * strideA ; B += (z % modB) * strideB ;
// C += z * strideC ; bias += (z % modB) * biasStride.
// TRANS_B == true means B is stored [N, K] row-major (used for Q @ K^T).
// -------------------------------------------------------------------------
template <bool TRANS_B>
__global__ void __launch_bounds__(256, 2) sgemm_kernel(
    const float* __restrict__ A, const float* __restrict__ Bm,
    float* __restrict__ C,
    int Md, int Nd, int Kd,
    int divA, int modB,
    long long strideA, long long strideB, long long strideC,
    float alpha, const float* __restrict__ bias, int biasStride)
{
    const int z = blockIdx.z;
    A  += (long long)(z / divA) * strideA;
    Bm += (long long)(z % modB) * strideB;
    C  += (long long)z * strideC;
    const float* bptr = bias ? (bias + (long long)(z % modB) * biasStride) : nullptr;

    __shared__ float As[8][128];
    __shared__ float Bs[8][128];

    const int tid  = threadIdx.x;
    const int tx   = tid & 15;
    const int ty   = tid >> 4;
    const int row0 = ty * 8;
    const int col0 = tx * 8;
    const int m0   = blockIdx.y * 128;
    const int n0   = blockIdx.x * 128;

    // Load-assignment indices
    const int aRow = tid >> 1;        // 0..127
    const int aCol = (tid & 1) * 4;   // 0 or 4
    const int bRow = tid >> 5;        // 0..7    (NN)
    const int bCol = (tid & 31) * 4;  // 0..124  (NN)

    float acc[8][8];
    #pragma unroll
    for (int i = 0; i < 8; i++)
        #pragma unroll
        for (int j = 0; j < 8; j++) acc[i][j] = 0.0f;

    for (int k0 = 0; k0 < Kd; k0 += 8) {
        // --- stage A tile (store k-major for vectorized smem reads) ---
        float4 av = *reinterpret_cast<const float4*>(
            A + (long long)(m0 + aRow) * Kd + (k0 + aCol));
        As[aCol + 0][aRow] = av.x;
        As[aCol + 1][aRow] = av.y;
        As[aCol + 2][aRow] = av.z;
        As[aCol + 3][aRow] = av.w;

        // --- stage B tile ---
        if (!TRANS_B) {
            float4 bv = *reinterpret_cast<const float4*>(
                Bm + (long long)(k0 + bRow) * Nd + (n0 + bCol));
            *reinterpret_cast<float4*>(&Bs[bRow][bCol]) = bv;
        } else {
            // B stored [N, K] row-major: Bs[k][n] = B[n0+n][k0+k]
            float4 bv = *reinterpret_cast<const float4*>(
                Bm + (long long)(n0 + aRow) * Kd + (k0 + aCol));
            Bs[aCol + 0][aRow] = bv.x;
            Bs[aCol + 1][aRow] = bv.y;
            Bs[aCol + 2][aRow] = bv.z;
            Bs[aCol + 3][aRow] = bv.w;
        }
        __syncthreads();

        // --- compute ---
        #pragma unroll
        for (int kk = 0; kk < 8; kk++) {
            float a[8], b[8];
            *reinterpret_cast<float4*>(a)     = *reinterpret_cast<const float4*>(&As[kk][row0]);
            *reinterpret_cast<float4*>(a + 4) = *reinterpret_cast<const float4*>(&As[kk][row0 + 4]);
            *reinterpret_cast<float4*>(b)     = *reinterpret_cast<const float4*>(&Bs[kk][col0]);
            *reinterpret_cast<float4*>(b + 4) = *reinterpret_cast<const float4*>(&Bs[kk][col0 + 4]);
            #pragma unroll
            for (int i = 0; i < 8; i++)
                #pragma unroll
                for (int j = 0; j < 8; j++)
                    acc[i][j] += a[i] * b[j];
        }
        __syncthreads();
    }

    // --- epilogue ---
    #pragma unroll
    for (int i = 0; i < 8; i++) {
        long long crow = (long long)(m0 + row0 + i) * Nd + n0;
        #pragma unroll
        for (int j = 0; j < 8; j += 4) {
            float4 o;
            o.x = acc[i][j + 0] * alpha;
            o.y = acc[i][j + 1] * alpha;
            o.z = acc[i][j + 2] * alpha;
            o.w = acc[i][j + 3] * alpha;
            if (bptr) {
                o.x += bptr[n0 + col0 + j + 0];
                o.y += bptr[n0 + col0 + j + 1];
                o.z += bptr[n0 + col0 + j + 2];
                o.w += bptr[n0 + col0 + j + 3];
            }
            *reinterpret_cast<float4*>(C + crow + col0 + j) = o;
        }
    }
}

// -------------------------------------------------------------------------
// Row softmax over N_=2048 columns. One block (256 threads) per row,
// 8 contiguous elements per thread.
// -------------------------------------------------------------------------
__global__ void __launch_bounds__(256) softmax_kernel(float* __restrict__ S)
{
    float* p = S + (long long)blockIdx.x * N_;
    const int tid = threadIdx.x;

    float4 v0 = *reinterpret_cast<const float4*>(p + tid * 8);
    float4 v1 = *reinterpret_cast<const float4*>(p + tid * 8 + 4);

    float m = fmaxf(fmaxf(fmaxf(v0.x, v0.y), fmaxf(v0.z, v0.w)),
                    fmaxf(fmaxf(v1.x, v1.y), fmaxf(v1.z, v1.w)));
    #pragma unroll
    for (int o = 16; o > 0; o >>= 1)
        m = fmaxf(m, __shfl_xor_sync(0xffffffffu, m, o));

    __shared__ float smax[8];
    __shared__ float ssum[8];
    if ((tid & 31) == 0) smax[tid >> 5] = m;
    __syncthreads();
    m = smax[0];
    #pragma unroll
    for (int i = 1; i < 8; i++) m = fmaxf(m, smax[i]);

    v0.x = __expf(v0.x - m); v0.y = __expf(v0.y - m);
    v0.z = __expf(v0.z - m); v0.w = __expf(v0.w - m);
    v1.x = __expf(v1.x - m); v1.y = __expf(v1.y - m);
    v1.z = __expf(v1.z - m); v1.w = __expf(v1.w - m);

    float s = v0.x + v0.y + v0.z + v0.w + v1.x + v1.y + v1.z + v1.w;
    #pragma unroll
    for (int o = 16; o > 0; o >>= 1)
        s += __shfl_xor_sync(0xffffffffu, s, o);
    if ((tid & 31) == 0) ssum[tid >> 5] = s;
    __syncthreads();
    s = 0.0f;
    #pragma unroll
    for (int i = 0; i < 8; i++) s += ssum[i];

    const float inv = 1.0f / s;
    v0.x *= inv; v0.y *= inv; v0.z *= inv; v0.w *= inv;
    v1.x *= inv; v1.y *= inv; v1.z *= inv; v1.w *= inv;

    *reinterpret_cast<float4*>(p + tid * 8)     = v0;
    *reinterpret_cast<float4*>(p + tid * 8 + 4) = v1;
}

// -------------------------------------------------------------------------
// Head-interleave: outs[b, m, d*H + h] = attn[b, h, m, d]
// One block per (b, m); smem tile with 516 padding for conflict-free writes.
// -------------------------------------------------------------------------
__global__ void __launch_bounds__(256) interleave_kernel(
    const float* __restrict__ attn, float* __restrict__ outs)
{
    const int m = blockIdx.x;
    const int b = blockIdx.y;
    __shared__ float t[H_][516];
    const int tid = threadIdx.x;

    #pragma unroll
    for (int i = 0; i < 16; i++) {
        int idx = tid + i * 256;            // 0..4095
        int h = idx >> 9;                   // /512
        int d = idx & 511;
        t[h][d] = attn[(((long long)(b * H_ + h) * M_ + m) << 9) + d];
    }
    __syncthreads();

    float* o = outs + ((long long)b * M_ + m) * HD_;
    #pragma unroll
    for (int i = 0; i < 16; i++) {
        int idx = tid + i * 256;
        o[idx] = t[idx & (H_ - 1)][idx >> 3];
    }
}

// -------------------------------------------------------------------------
// Launch
// -------------------------------------------------------------------------
extern "C" void kernel_launch(void* const* d_in, const int* in_sizes, int n_in,
                              void* d_out, int out_size)
{
    const float* k  = (const float*)d_in[0];
    const float* v  = (const float*)d_in[1];
    const float* q  = (const float*)d_in[2];
    const float* Wk = (const float*)d_in[3];
    const float* bk = (const float*)d_in[4];
    const float* Wv = (const float*)d_in[5];
    const float* bv = (const float*)d_in[6];
    const float* Wq = (const float*)d_in[7];
    const float* bq = (const float*)d_in[8];
    const float* Wo = (const float*)d_in[9];
    const float* bo = (const float*)d_in[10];
    float* out = (float*)d_out;

    float *kp, *vp, *qp, *sc, *at, *os;
    cudaGetSymbolAddress((void**)&kp, g_kp);
    cudaGetSymbolAddress((void**)&vp, g_vp);
    cudaGetSymbolAddress((void**)&qp, g_qp);
    cudaGetSymbolAddress((void**)&sc, g_scores);
    cudaGetSymbolAddress((void**)&at, g_attn);
    cudaGetSymbolAddress((void**)&os, g_outs);

    const long long sND = (long long)N_ * D_;   // 2048*512
    const long long sDD = (long long)D_ * D_;   // 512*512
    const long long sMN = (long long)M_ * N_;   // 2048*2048
    const long long sMH = (long long)M_ * HD_;  // 2048*4096
    const long long sMD = (long long)M_ * D_;   // 2048*512

    // 1) Per-head projections: X[b] (2048x512) @ W[h] (512x512) + bias
    {
        dim3 grid(D_ / 128, N_ / 128, BH_);
        sgemm_kernel<false><<<grid, 256>>>(k, Wk, kp, N_, D_, D_,
                                           H_, H_, sND, sDD, sND,
                                           1.0f, bk, D_);
        sgemm_kernel<false><<<grid, 256>>>(v, Wv, vp, N_, D_, D_,
                                           H_, H_, sND, sDD, sND,
                                           1.0f, bv, D_);
        sgemm_kernel<false><<<grid, 256>>>(q, Wq, qp, M_, D_, D_,
                                           H_, H_, sND, sDD, sND,
                                           1.0f, bq, D_);
    }

    // 2) scores = (q' @ k'^T) / sqrt(D)   [per (b,h): 2048x2048, K=512]
    {
        dim3 grid(N_ / 128, M_ / 128, BH_);
        const float scale = 0.044194173824159216f;  // 1/sqrt(512)
        sgemm_kernel<true><<<grid, 256>>>(qp, kp, sc, M_, N_, D_,
                                          1, BH_, sMD, sND, sMN,
                                          scale, nullptr, 0);
    }

    // 3) row softmax over N
    softmax_kernel<<<BH_ * M_, 256>>>(sc);

    // 4) attn = P @ v'   [per (b,h): 2048x512, K=2048]
    {
        dim3 grid(D_ / 128, M_ / 128, BH_);
        sgemm_kernel<false><<<grid, 256>>>(sc, vp, at, M_, D_, N_,
                                           1, BH_, sMN, sND, sMD,
                                           1.0f, nullptr, 0);
    }

    // 5) interleave heads: [B,H,M,D] -> [B,M,D*H] (d-major, h-minor)
    {
        dim3 grid(M_, B_);
        interleave_kernel<<<grid, 256>>>(at, os);
    }

    // 6) rep = outs @ Wo + bo   [per b: 2048x512, K=4096]
    {
        dim3 grid(D_ / 128, M_ / 128, B_);
        sgemm_kernel<false><<<grid, 256>>>(os, Wo, out, M_, D_, HD_,
                                           1, 1, sMH, 0, sMD,
                                           1.0f, bo, 0);
    }
}

// round 4
// speedup vs baseline: 2.9691x; 2.9691x over previous
#include <cuda_runtime.h>
#include <cuda_fp16.h>
#include <cstdint>

#define B_  8
#define N_  2048
#define M_  2048
#define D_  512
#define H_  8
#define BH_ (B_ * H_)
#define HD_ (H_ * D_)

// -------------------------------------------------------------------------
// Device scratch (fp16 hi/lo split operands + fp32 intermediates)
// -------------------------------------------------------------------------
__device__ __half g_kc_hi[(size_t)B_ * N_ * D_], g_kc_lo[(size_t)B_ * N_ * D_];
__device__ __half g_vc_hi[(size_t)B_ * N_ * D_], g_vc_lo[(size_t)B_ * N_ * D_];
__device__ __half g_qc_hi[(size_t)B_ * M_ * D_], g_qc_lo[(size_t)B_ * M_ * D_];
__device__ __half g_WkT_hi[(size_t)H_ * D_ * D_], g_WkT_lo[(size_t)H_ * D_ * D_];
__device__ __half g_WvT_hi[(size_t)H_ * D_ * D_], g_WvT_lo[(size_t)H_ * D_ * D_];
__device__ __half g_WqT_hi[(size_t)H_ * D_ * D_], g_WqT_lo[(size_t)H_ * D_ * D_];
__device__ __half g_WoT_hi[(size_t)D_ * HD_],     g_WoT_lo[(size_t)D_ * HD_];
__device__ __half g_kp_hi[(size_t)BH_ * N_ * D_], g_kp_lo[(size_t)BH_ * N_ * D_];
__device__ __half g_qp_hi[(size_t)BH_ * M_ * D_], g_qp_lo[(size_t)BH_ * M_ * D_];
__device__ __half g_vT_hi[(size_t)BH_ * D_ * N_], g_vT_lo[(size_t)BH_ * D_ * N_];
__device__ float  g_scores[(size_t)BH_ * M_ * N_];
__device__ __half g_P_hi[(size_t)BH_ * M_ * N_],  g_P_lo[(size_t)BH_ * M_ * N_];
__device__ float  g_attn[(size_t)BH_ * M_ * D_];
__device__ __half g_outs_hi[(size_t)B_ * M_ * HD_], g_outs_lo[(size_t)B_ * M_ * HD_];

// -------------------------------------------------------------------------
// PTX helpers (all family-baseline instructions: sm_80-era)
// -------------------------------------------------------------------------
__device__ __forceinline__ uint32_t smem_to_u32(const void* p) {
    uint32_t a;
    asm("{ .reg .u64 t; cvta.to.shared.u64 t, %1; cvt.u32.u64 %0, t; }" : "=r"(a) : "l"(p));
    return a;
}
__device__ __forceinline__ void cp16(uint32_t dst, const void* src) {
    asm volatile("cp.async.cg.shared.global [%0], [%1], 16;" :: "r"(dst), "l"(src));
}
#define CP_COMMIT() asm volatile("cp.async.commit_group;" ::: "memory")
#define CP_WAIT2()  asm volatile("cp.async.wait_group 2;" ::: "memory")

__device__ __forceinline__ void ldsm4(uint32_t* r, uint32_t addr) {
    asm volatile("ldmatrix.sync.aligned.m8n8.x4.shared.b16 {%0,%1,%2,%3}, [%4];"
                 : "=r"(r[0]), "=r"(r[1]), "=r"(r[2]), "=r"(r[3]) : "r"(addr));
}
__device__ __forceinline__ void mma16816(float* c, const uint32_t* a,
                                         uint32_t b0, uint32_t b1) {
    asm volatile("mma.sync.aligned.m16n8k16.row.col.f32.f16.f16.f32 "
                 "{%0,%1,%2,%3}, {%4,%5,%6,%7}, {%8,%9}, {%0,%1,%2,%3};"
                 : "+f"(c[0]), "+f"(c[1]), "+f"(c[2]), "+f"(c[3])
                 : "r"(a[0]), "r"(a[1]), "r"(a[2]), "r"(a[3]), "r"(b0), "r"(b1));
}
__device__ __forceinline__ void split(float v, __half& h, __half& l) {
    h = __float2half_rn(v);
    l = __float2half_rn(v - __half2float(h));
}

// -------------------------------------------------------------------------
// fp16x3 tensor-core GEMM.
// C[z] = alpha * A[z] @ B[z]^T (+ bias)
// A: [Md, Kd] fp16 hi/lo (row-major).  B: [Nd, Kd] fp16 hi/lo (K-major).
// EPI: 0 = fp32 out [Md,Nd]; 1 = fp16 hi/lo pair out; 2 = fp16 pair
// transposed out (C[n*Md+m]).
// CTA 128x128, BK=64, 256 threads (8 warps, 2(M) x 4(N)), 3-stage cp.async
// pipeline, 64KB/stage (A_hi, A_lo, B_hi, B_lo each 16KB), XOR swizzle.
// -------------------------------------------------------------------------
#define STAGE_BYTES 65536
#define SHM_TOTAL   (3 * STAGE_BYTES)

template <int EPI>
__global__ void __launch_bounds__(256, 1) hgemm_kernel(
    const __half* __restrict__ Ah, const __half* __restrict__ Al,
    const __half* __restrict__ Bh, const __half* __restrict__ Bl,
    float* __restrict__ Cf, __half* __restrict__ Ch, __half* __restrict__ Cl,
    int Md, int Nd, int Kd, int divA, int modB,
    long long strideA, long long strideB, long long strideC,
    float alpha, const float* __restrict__ bias, int biasStride)
{
    extern __shared__ char smem[];
    const uint32_t sm0 = smem_to_u32(smem);
    const int tid = threadIdx.x;
    const int wid = tid >> 5, lane = tid & 31;
    const int wm = wid >> 2, wn = wid & 3;      // 2 x 4 warp grid

    const int z = blockIdx.z;
    Ah += (long long)(z / divA) * strideA;
    Al += (long long)(z / divA) * strideA;
    Bh += (long long)(z % modB) * strideB;
    Bl += (long long)(z % modB) * strideB;
    const long long coff = (long long)z * strideC;
    const float* bptr = bias ? (bias + (long long)(z % modB) * biasStride) : nullptr;
    const int m0 = blockIdx.y * 128;
    const int n0 = blockIdx.x * 128;

    const int nIter = Kd >> 6;

    // ---- cp.async stage issue: 4 chunks x 4 arrays per thread ----
    auto issue = [&](int it, int st) {
        const uint32_t sb = sm0 + st * STAGE_BYTES;
        const long long kbase = (long long)it * 64;
        #pragma unroll
        for (int i = 0; i < 4; i++) {
            int ci = tid + i * 256;          // 0..1023
            int row = ci >> 3;               // 0..127
            int kc8 = ci & 7;                // 16B chunk within 128B row
            uint32_t doff = row * 128 + ((kc8 * 16) ^ ((row & 7) << 4));
            const __half* sa = Ah + (long long)(m0 + row) * Kd + kbase + kc8 * 8;
            const __half* sal = Al + (long long)(m0 + row) * Kd + kbase + kc8 * 8;
            const __half* sbh = Bh + (long long)(n0 + row) * Kd + kbase + kc8 * 8;
            const __half* sbl = Bl + (long long)(n0 + row) * Kd + kbase + kc8 * 8;
            cp16(sb + doff,             sa);
            cp16(sb + 16384 + doff,     sal);
            cp16(sb + 32768 + doff,     sbh);
            cp16(sb + 49152 + doff,     sbl);
        }
    };

    float acc[4][4][4];
    #pragma unroll
    for (int i = 0; i < 4; i++)
        #pragma unroll
        for (int j = 0; j < 4; j++)
            #pragma unroll
            for (int r = 0; r < 4; r++) acc[i][j][r] = 0.0f;

    // prologue: 3 stages
    issue(0, 0); CP_COMMIT();
    issue(1, 1); CP_COMMIT();
    issue(2, 2); CP_COMMIT();

    // ldmatrix lane-address components
    // A: frag mf at k-step kc: row = wm*64 + mf*16 + (lane&15), chunk (lane>>4)
    const int arow_l = wm * 64 + (lane & 15);
    const int akch   = (lane >> 4) << 4;     // 0 or 16 bytes
    // B: group ng: n = wn*32 + ng*16 + ((lane>>4)<<3) + (lane&7), chunk (lane>>3)&1
    const int brow_l = wn * 32 + ((lane >> 4) << 3) + (lane & 7);
    const int bkch   = ((lane >> 3) & 1) << 4;

    for (int it = 0; it < nIter; it++) {
        const int st = it - (it / 3) * 3;
        CP_WAIT2();
        __syncthreads();

        const uint32_t sb = sm0 + st * STAGE_BYTES;
        #pragma unroll
        for (int kc = 0; kc < 4; kc++) {
            uint32_t ah[4][4], al[4][4], bh[2][4], bl[2][4];
            #pragma unroll
            for (int mf = 0; mf < 4; mf++) {
                int row = arow_l + mf * 16;
                uint32_t addr = sb + row * 128 + ((kc * 32 + akch) ^ ((row & 7) << 4));
                ldsm4(ah[mf], addr);
                ldsm4(al[mf], addr + 16384);
            }
            #pragma unroll
            for (int ng = 0; ng < 2; ng++) {
                int row = brow_l + ng * 16;
                uint32_t addr = sb + 32768 + row * 128 +
                                ((kc * 32 + bkch) ^ ((row & 7) << 4));
                ldsm4(bh[ng], addr);
                ldsm4(bl[ng], addr + 16384);
            }
            #pragma unroll
            for (int mf = 0; mf < 4; mf++) {
                #pragma unroll
                for (int nf = 0; nf < 4; nf++) {
                    const int ng = nf >> 1, j = nf & 1;
                    mma16816(acc[mf][nf], ah[mf], bh[ng][2 * j], bh[ng][2 * j + 1]);
                    mma16816(acc[mf][nf], al[mf], bh[ng][2 * j], bh[ng][2 * j + 1]);
                    mma16816(acc[mf][nf], ah[mf], bl[ng][2 * j], bl[ng][2 * j + 1]);
                }
            }
        }
        __syncthreads();
        if (it + 3 < nIter) issue(it + 3, st);
        CP_COMMIT();
    }

    // ---- epilogue ----
    const int g  = lane >> 2;
    const int cp2 = (lane & 3) * 2;
    #pragma unroll
    for (int mf = 0; mf < 4; mf++) {
        #pragma unroll
        for (int nf = 0; nf < 4; nf++) {
            int row0 = m0 + wm * 64 + mf * 16 + g;
            int row1 = row0 + 8;
            int col  = n0 + wn * 32 + nf * 8 + cp2;
            float v00 = acc[mf][nf][0] * alpha;
            float v01 = acc[mf][nf][1] * alpha;
            float v10 = acc[mf][nf][2] * alpha;
            float v11 = acc[mf][nf][3] * alpha;
            if (bptr) {
                float b0 = bptr[col], b1 = bptr[col + 1];
                v00 += b0; v01 += b1; v10 += b0; v11 += b1;
            }
            if (EPI == 0) {
                *reinterpret_cast<float2*>(Cf + coff + (long long)row0 * Nd + col) =
                    make_float2(v00, v01);
                *reinterpret_cast<float2*>(Cf + coff + (long long)row1 * Nd + col) =
                    make_float2(v10, v11);
            } else if (EPI == 1) {
                __half h00, l00, h01, l01, h10, l10, h11, l11;
                split(v00, h00, l00); split(v01, h01, l01);
                split(v10, h10, l10); split(v11, h11, l11);
                __half2 hh0; hh0.x = h00; hh0.y = h01;
                __half2 ll0; ll0.x = l00; ll0.y = l01;
                __half2 hh1; hh1.x = h10; hh1.y = h11;
                __half2 ll1; ll1.x = l10; ll1.y = l11;
                *reinterpret_cast<__half2*>(Ch + coff + (long long)row0 * Nd + col) = hh0;
                *reinterpret_cast<__half2*>(Cl + coff + (long long)row0 * Nd + col) = ll0;
                *reinterpret_cast<__half2*>(Ch + coff + (long long)row1 * Nd + col) = hh1;
                *reinterpret_cast<__half2*>(Cl + coff + (long long)row1 * Nd + col) = ll1;
            } else {
                __half h, l;
                split(v00, h, l);
                Ch[coff + (long long)col * Md + row0] = h;
                Cl[coff + (long long)col * Md + row0] = l;
                split(v01, h, l);
                Ch[coff + (long long)(col + 1) * Md + row0] = h;
                Cl[coff + (long long)(col + 1) * Md + row0] = l;
                split(v10, h, l);
                Ch[coff + (long long)col * Md + row1] = h;
                Cl[coff + (long long)col * Md + row1] = l;
                split(v11, h, l);
                Ch[coff + (long long)(col + 1) * Md + row1] = h;
                Cl[coff + (long long)(col + 1) * Md + row1] = l;
            }
        }
    }
}

// -------------------------------------------------------------------------
// fp32 -> fp16 hi/lo split (elementwise), float4 granularity
// -------------------------------------------------------------------------
__global__ void __launch_bounds__(256) convsplit_kernel(
    const float* __restrict__ src, __half* __restrict__ hi,
    __half* __restrict__ lo, size_t n4)
{
    size_t i = (size_t)blockIdx.x * 256 + threadIdx.x;
    if (i >= n4) return;
    float4 v = reinterpret_cast<const float4*>(src)[i];
    __half h0, l0, h1, l1, h2, l2, h3, l3;
    split(v.x, h0, l0); split(v.y, h1, l1);
    split(v.z, h2, l2); split(v.w, h3, l3);
    __half2 ha; ha.x = h0; ha.y = h1;
    __half2 hb; hb.x = h2; hb.y = h3;
    __half2 la; la.x = l0; la.y = l1;
    __half2 lb; lb.x = l2; lb.y = l3;
    reinterpret_cast<__half2*>(hi)[2 * i]     = ha;
    reinterpret_cast<__half2*>(hi)[2 * i + 1] = hb;
    reinterpret_cast<__half2*>(lo)[2 * i]     = la;
    reinterpret_cast<__half2*>(lo)[2 * i + 1] = lb;
}

// -------------------------------------------------------------------------
// Batched transpose + split: dst_hi/lo[z][c][r] = split(src[z][r][c])
// -------------------------------------------------------------------------
__global__ void __launch_bounds__(256) transpose_split_kernel(
    const float* __restrict__ src, __half* __restrict__ hi,
    __half* __restrict__ lo, int R, int C)
{
    __shared__ float t[32][33];
    const size_t zoff = (size_t)blockIdx.z * R * C;
    int tx = threadIdx.x, ty = threadIdx.y;
    int x = blockIdx.x * 32 + tx;
    int y = blockIdx.y * 32 + ty;
    #pragma unroll
    for (int j = 0; j < 32; j += 8)
        t[ty + j][tx] = src[zoff + (size_t)(y + j) * C + x];
    __syncthreads();
    int x2 = blockIdx.y * 32 + tx;
    int y2 = blockIdx.x * 32 + ty;
    #pragma unroll
    for (int j = 0; j < 32; j += 8) {
        float v = t[tx][ty + j];
        __half h, l;
        split(v, h, l);
        hi[zoff + (size_t)(y2 + j) * R + x2] = h;
        lo[zoff + (size_t)(y2 + j) * R + x2] = l;
    }
}

// -------------------------------------------------------------------------
// Row softmax over N_=2048, emits fp16 hi/lo probability arrays.
// -------------------------------------------------------------------------
__global__ void __launch_bounds__(256) softmax_kernel(
    const float* __restrict__ S, __half* __restrict__ Ph, __half* __restrict__ Pl)
{
    const long long roff = (long long)blockIdx.x * N_;
    const float* p = S + roff;
    const int tid = threadIdx.x;

    float4 v0 = *reinterpret_cast<const float4*>(p + tid * 8);
    float4 v1 = *reinterpret_cast<const float4*>(p + tid * 8 + 4);

    float m = fmaxf(fmaxf(fmaxf(v0.x, v0.y), fmaxf(v0.z, v0.w)),
                    fmaxf(fmaxf(v1.x, v1.y), fmaxf(v1.z, v1.w)));
    #pragma unroll
    for (int o = 16; o > 0; o >>= 1)
        m = fmaxf(m, __shfl_xor_sync(0xffffffffu, m, o));

    __shared__ float smax[8];
    __shared__ float ssum[8];
    if ((tid & 31) == 0) smax[tid >> 5] = m;
    __syncthreads();
    m = smax[0];
    #pragma unroll
    for (int i = 1; i < 8; i++) m = fmaxf(m, smax[i]);

    v0.x = __expf(v0.x - m); v0.y = __expf(v0.y - m);
    v0.z = __expf(v0.z - m); v0.w = __expf(v0.w - m);
    v1.x = __expf(v1.x - m); v1.y = __expf(v1.y - m);
    v1.z = __expf(v1.z - m); v1.w = __expf(v1.w - m);

    float s = v0.x + v0.y + v0.z + v0.w + v1.x + v1.y + v1.z + v1.w;
    #pragma unroll
    for (int o = 16; o > 0; o >>= 1)
        s += __shfl_xor_sync(0xffffffffu, s, o);
    if ((tid & 31) == 0) ssum[tid >> 5] = s;
    __syncthreads();
    s = 0.0f;
    #pragma unroll
    for (int i = 0; i < 8; i++) s += ssum[i];

    const float inv = 1.0f / s;
    float pv[8] = { v0.x * inv, v0.y * inv, v0.z * inv, v0.w * inv,
                    v1.x * inv, v1.y * inv, v1.z * inv, v1.w * inv };
    __half2 hh[4], ll[4];
    #pragma unroll
    for (int i = 0; i < 4; i++) {
        __half h0, l0, h1, l1;
        split(pv[2 * i], h0, l0);
        split(pv[2 * i + 1], h1, l1);
        hh[i].x = h0; hh[i].y = h1;
        ll[i].x = l0; ll[i].y = l1;
    }
    *reinterpret_cast<uint4*>(Ph + roff + tid * 8) = *reinterpret_cast<uint4*>(hh);
    *reinterpret_cast<uint4*>(Pl + roff + tid * 8) = *reinterpret_cast<uint4*>(ll);
}

// -------------------------------------------------------------------------
// Head-interleave + split: outs[b, m, d*H + h] = attn[b, h, m, d]
// -------------------------------------------------------------------------
__global__ void __launch_bounds__(256) interleave_kernel(
    const float* __restrict__ attn, __half* __restrict__ oh, __half* __restrict__ ol)
{
    const int m = blockIdx.x;
    const int b = blockIdx.y;
    __shared__ float t[H_][516];
    const int tid = threadIdx.x;

    #pragma unroll
    for (int i = 0; i < 16; i++) {
        int idx = tid + i * 256;
        int h = idx >> 9;
        int d = idx & 511;
        t[h][d] = attn[(((long long)(b * H_ + h) * M_ + m) << 9) + d];
    }
    __syncthreads();

    const long long ob = ((long long)b * M_ + m) * HD_;
    #pragma unroll
    for (int i = 0; i < 16; i++) {
        int idx = tid + i * 256;
        float v = t[idx & (H_ - 1)][idx >> 3];
        __half h, l;
        split(v, h, l);
        oh[ob + idx] = h;
        ol[ob + idx] = l;
    }
}

// -------------------------------------------------------------------------
// Launch
// -------------------------------------------------------------------------
extern "C" void kernel_launch(void* const* d_in, const int* in_sizes, int n_in,
                              void* d_out, int out_size)
{
    (void)in_sizes; (void)n_in; (void)out_size;
    const float* k  = (const float*)d_in[0];
    const float* v  = (const float*)d_in[1];
    const float* q  = (const float*)d_in[2];
    const float* Wk = (const float*)d_in[3];
    const float* bk = (const float*)d_in[4];
    const float* Wv = (const float*)d_in[5];
    const float* bv = (const float*)d_in[6];
    const float* Wq = (const float*)d_in[7];
    const float* bq = (const float*)d_in[8];
    const float* Wo = (const float*)d_in[9];
    const float* bo = (const float*)d_in[10];
    float* out = (float*)d_out;

    __half *kc_hi, *kc_lo, *vc_hi, *vc_lo, *qc_hi, *qc_lo;
    __half *WkT_hi, *WkT_lo, *WvT_hi, *WvT_lo, *WqT_hi, *WqT_lo, *WoT_hi, *WoT_lo;
    __half *kp_hi, *kp_lo, *qp_hi, *qp_lo, *vT_hi, *vT_lo;
    __half *P_hi, *P_lo, *outs_hi, *outs_lo;
    float *sc, *at;
    cudaGetSymbolAddress((void**)&kc_hi, g_kc_hi);  cudaGetSymbolAddress((void**)&kc_lo, g_kc_lo);
    cudaGetSymbolAddress((void**)&vc_hi, g_vc_hi);  cudaGetSymbolAddress((void**)&vc_lo, g_vc_lo);
    cudaGetSymbolAddress((void**)&qc_hi, g_qc_hi);  cudaGetSymbolAddress((void**)&qc_lo, g_qc_lo);
    cudaGetSymbolAddress((void**)&WkT_hi, g_WkT_hi); cudaGetSymbolAddress((void**)&WkT_lo, g_WkT_lo);
    cudaGetSymbolAddress((void**)&WvT_hi, g_WvT_hi); cudaGetSymbolAddress((void**)&WvT_lo, g_WvT_lo);
    cudaGetSymbolAddress((void**)&WqT_hi, g_WqT_hi); cudaGetSymbolAddress((void**)&WqT_lo, g_WqT_lo);
    cudaGetSymbolAddress((void**)&WoT_hi, g_WoT_hi); cudaGetSymbolAddress((void**)&WoT_lo, g_WoT_lo);
    cudaGetSymbolAddress((void**)&kp_hi, g_kp_hi);  cudaGetSymbolAddress((void**)&kp_lo, g_kp_lo);
    cudaGetSymbolAddress((void**)&qp_hi, g_qp_hi);  cudaGetSymbolAddress((void**)&qp_lo, g_qp_lo);
    cudaGetSymbolAddress((void**)&vT_hi, g_vT_hi);  cudaGetSymbolAddress((void**)&vT_lo, g_vT_lo);
    cudaGetSymbolAddress((void**)&P_hi, g_P_hi);    cudaGetSymbolAddress((void**)&P_lo, g_P_lo);
    cudaGetSymbolAddress((void**)&outs_hi, g_outs_hi); cudaGetSymbolAddress((void**)&outs_lo, g_outs_lo);
    cudaGetSymbolAddress((void**)&sc, g_scores);
    cudaGetSymbolAddress((void**)&at, g_attn);

    const long long sND = (long long)N_ * D_;
    const long long sDD = (long long)D_ * D_;
    const long long sMN = (long long)M_ * N_;
    const long long sMH = (long long)M_ * HD_;
    const long long sMD = (long long)M_ * D_;

    cudaFuncSetAttribute(hgemm_kernel<0>, cudaFuncAttributeMaxDynamicSharedMemorySize, SHM_TOTAL);
    cudaFuncSetAttribute(hgemm_kernel<1>, cudaFuncAttributeMaxDynamicSharedMemorySize, SHM_TOTAL);
    cudaFuncSetAttribute(hgemm_kernel<2>, cudaFuncAttributeMaxDynamicSharedMemorySize, SHM_TOTAL);

    // 0) split inputs, transpose+split weights
    {
        size_t n4 = (size_t)B_ * N_ * D_ / 4;
        int gb = (int)((n4 + 255) / 256);
        convsplit_kernel<<<gb, 256>>>(k, kc_hi, kc_lo, n4);
        convsplit_kernel<<<gb, 256>>>(v, vc_hi, vc_lo, n4);
        convsplit_kernel<<<gb, 256>>>(q, qc_hi, qc_lo, n4);
        dim3 tb(32, 8);
        transpose_split_kernel<<<dim3(D_ / 32, D_ / 32, H_), tb>>>(Wk, WkT_hi, WkT_lo, D_, D_);
        transpose_split_kernel<<<dim3(D_ / 32, D_ / 32, H_), tb>>>(Wv, WvT_hi, WvT_lo, D_, D_);
        transpose_split_kernel<<<dim3(D_ / 32, D_ / 32, H_), tb>>>(Wq, WqT_hi, WqT_lo, D_, D_);
        transpose_split_kernel<<<dim3(D_ / 32, HD_ / 32, 1), tb>>>(Wo, WoT_hi, WoT_lo, HD_, D_);
    }

    // 1) projections: k' & q' (pair out), v' (pair out, transposed)
    {
        dim3 grid(D_ / 128, N_ / 128, BH_);
        hgemm_kernel<1><<<grid, 256, SHM_TOTAL>>>(kc_hi, kc_lo, WkT_hi, WkT_lo,
            nullptr, kp_hi, kp_lo, N_, D_, D_, H_, H_, sND, sDD, sND, 1.0f, bk, D_);
        hgemm_kernel<1><<<grid, 256, SHM_TOTAL>>>(qc_hi, qc_lo, WqT_hi, WqT_lo,
            nullptr, qp_hi, qp_lo, M_, D_, D_, H_, H_, sND, sDD, sND, 1.0f, bq, D_);
        hgemm_kernel<2><<<grid, 256, SHM_TOTAL>>>(vc_hi, vc_lo, WvT_hi, WvT_lo,
            nullptr, vT_hi, vT_lo, N_, D_, D_, H_, H_, sND, sDD, sND, 1.0f, bv, D_);
    }

    // 2) scores = (q' @ k'^T) / sqrt(D)
    {
        dim3 grid(N_ / 128, M_ / 128, BH_);
        const float scale = 0.044194173824159216f;
        hgemm_kernel<0><<<grid, 256, SHM_TOTAL>>>(qp_hi, qp_lo, kp_hi, kp_lo,
            sc, nullptr, nullptr, M_, N_, D_, 1, BH_, sMD, sND, sMN, scale, nullptr, 0);
    }

    // 3) softmax -> P hi/lo
    softmax_kernel<<<BH_ * M_, 256>>>(sc, P_hi, P_lo);

    // 4) attn = P @ v'
    {
        dim3 grid(D_ / 128, M_ / 128, BH_);
        hgemm_kernel<0><<<grid, 256, SHM_TOTAL>>>(P_hi, P_lo, vT_hi, vT_lo,
            at, nullptr, nullptr, M_, D_, N_, 1, BH_, sMN, sND, sMD, 1.0f, nullptr, 0);
    }

    // 5) interleave -> outs hi/lo
    interleave_kernel<<<dim3(M_, B_), 256>>>(at, outs_hi, outs_lo);

    // 6) out = outs @ Wo + bo
    {
        dim3 grid(D_ / 128, M_ / 128, B_);
        hgemm_kernel<0><<<grid, 256, SHM_TOTAL>>>(outs_hi, outs_lo, WoT_hi, WoT_lo,
            out, nullptr, nullptr, M_, D_, HD_, 1, 1, sMH, 0, sMD, 1.0f, bo, 0);
    }
}

// round 7
// speedup vs baseline: 2.9988x; 1.0100x over previous
#include <cuda_runtime.h>
#include <cuda_fp16.h>
#include <cstdint>

#define B_  8
#define N_  2048
#define M_  2048
#define D_  512
#define H_  8
#define BH_ (B_ * H_)
#define HD_ (H_ * D_)

// -------------------------------------------------------------------------
// Device scratch (fp16 hi/lo split operands + fp32 intermediates)
// -------------------------------------------------------------------------
__device__ __half g_kc_hi[(size_t)B_ * N_ * D_], g_kc_lo[(size_t)B_ * N_ * D_];
__device__ __half g_vc_hi[(size_t)B_ * N_ * D_], g_vc_lo[(size_t)B_ * N_ * D_];
__device__ __half g_qc_hi[(size_t)B_ * M_ * D_], g_qc_lo[(size_t)B_ * M_ * D_];
__device__ __half g_WkT_hi[(size_t)H_ * D_ * D_], g_WkT_lo[(size_t)H_ * D_ * D_];
__device__ __half g_WvT_hi[(size_t)H_ * D_ * D_], g_WvT_lo[(size_t)H_ * D_ * D_];
__device__ __half g_WqT_hi[(size_t)H_ * D_ * D_], g_WqT_lo[(size_t)H_ * D_ * D_];
__device__ __half g_WoP_hi[(size_t)D_ * HD_],     g_WoP_lo[(size_t)D_ * HD_];   // [n=512][k=h*512+d]
__device__ __half g_kp_hi[(size_t)BH_ * N_ * D_], g_kp_lo[(size_t)BH_ * N_ * D_];
__device__ __half g_qp_hi[(size_t)BH_ * M_ * D_], g_qp_lo[(size_t)BH_ * M_ * D_];
__device__ __half g_vT_hi[(size_t)BH_ * D_ * N_], g_vT_lo[(size_t)BH_ * D_ * N_];
__device__ float  g_scores[(size_t)BH_ * M_ * N_];
__device__ __half g_P_hi[(size_t)BH_ * M_ * N_],  g_P_lo[(size_t)BH_ * M_ * N_];
__device__ __half g_at_hi[(size_t)BH_ * M_ * D_], g_at_lo[(size_t)BH_ * M_ * D_];

// -------------------------------------------------------------------------
// PTX helpers (family-baseline instructions only)
// -------------------------------------------------------------------------
__device__ __forceinline__ uint32_t smem_to_u32(const void* p) {
    uint32_t a;
    asm("{ .reg .u64 t; cvta.to.shared.u64 t, %1; cvt.u32.u64 %0, t; }" : "=r"(a) : "l"(p));
    return a;
}
__device__ __forceinline__ void cp16(uint32_t dst, const void* src) {
    asm volatile("cp.async.cg.shared.global [%0], [%1], 16;" :: "r"(dst), "l"(src));
}
#define CP_COMMIT() asm volatile("cp.async.commit_group;" ::: "memory")
#define CP_WAIT2()  asm volatile("cp.async.wait_group 2;" ::: "memory")

__device__ __forceinline__ void ldsm4(uint32_t* r, uint32_t addr) {
    asm volatile("ldmatrix.sync.aligned.m8n8.x4.shared.b16 {%0,%1,%2,%3}, [%4];"
                 : "=r"(r[0]), "=r"(r[1]), "=r"(r[2]), "=r"(r[3]) : "r"(addr));
}
__device__ __forceinline__ void mma16816(float* c, const uint32_t* a,
                                         uint32_t b0, uint32_t b1) {
    asm volatile("mma.sync.aligned.m16n8k16.row.col.f32.f16.f16.f32 "
                 "{%0,%1,%2,%3}, {%4,%5,%6,%7}, {%8,%9}, {%0,%1,%2,%3};"
                 : "+f"(c[0]), "+f"(c[1]), "+f"(c[2]), "+f"(c[3])
                 : "r"(a[0]), "r"(a[1]), "r"(a[2]), "r"(a[3]), "r"(b0), "r"(b1));
}
__device__ __forceinline__ void split(float v, __half& h, __half& l) {
    h = __float2half_rn(v);
    l = __float2half_rn(v - __half2float(h));
}

// -------------------------------------------------------------------------
// fp16x3 tensor-core GEMM.  C[z] = alpha * A[z] @ B[z]^T (+ bias)
// A: [Md, Kd] fp16 hi/lo row-major.  B: [Nd, Kd] fp16 hi/lo K-major.
// EPI: 0 = fp32 out; 1 = fp16 hi/lo pair out; 2 = fp16 pair transposed out.
// GA:  gather A from attention layout [h][m][d] with k = h*512 + d
//      (A base pre-offset per batch; BK=64 block never crosses a head).
// CTA 128x128, BK=64, 256 threads (2x4 warps), 3-stage cp.async pipeline.
// -------------------------------------------------------------------------
#define STAGE_BYTES 65536
#define SHM_TOTAL   (3 * STAGE_BYTES)

template <int EPI, bool GA>
__global__ void __launch_bounds__(256, 1) hgemm_kernel(
    const __half* __restrict__ Ah, const __half* __restrict__ Al,
    const __half* __restrict__ Bh, const __half* __restrict__ Bl,
    float* __restrict__ Cf, __half* __restrict__ Ch, __half* __restrict__ Cl,
    int Md, int Nd, int Kd, int divA, int modB,
    long long strideA, long long strideB, long long strideC,
    float alpha, const float* __restrict__ bias, int biasStride)
{
    extern __shared__ char smem[];
    const uint32_t sm0 = smem_to_u32(smem);
    const int tid = threadIdx.x;
    const int wid = tid >> 5, lane = tid & 31;
    const int wm = wid >> 2, wn = wid & 3;      // 2 x 4 warp grid

    const int z = blockIdx.z;
    Ah += (long long)(z / divA) * strideA;
    Al += (long long)(z / divA) * strideA;
    Bh += (long long)(z % modB) * strideB;
    Bl += (long long)(z % modB) * strideB;
    const long long coff = (long long)z * strideC;
    const float* bptr = bias ? (bias + (long long)(z % modB) * biasStride) : nullptr;
    const int m0 = blockIdx.y * 128;
    const int n0 = blockIdx.x * 128;

    const int nIter = Kd >> 6;

    // ---- cp.async stage issue ----
    auto issue = [&](int it, int st) {
        const uint32_t sb = sm0 + st * STAGE_BYTES;
        const int kb = it * 64;
        // GA decomposition: head index + within-head offset (BK block stays in one head)
        const long long ga_off = GA ? ((long long)(kb >> 9) * ((long long)M_ * D_) + (kb & 511))
                                    : 0;
        #pragma unroll
        for (int i = 0; i < 4; i++) {
            int ci = tid + i * 256;          // 0..1023
            int row = ci >> 3;               // 0..127
            int kc8 = ci & 7;                // 16B chunk within 128B row
            uint32_t doff = row * 128 + ((kc8 * 16) ^ ((row & 7) << 4));
            const __half *sa, *sal;
            if (GA) {
                sa  = Ah + ga_off + (long long)(m0 + row) * D_ + kc8 * 8;
                sal = Al + ga_off + (long long)(m0 + row) * D_ + kc8 * 8;
            } else {
                sa  = Ah + (long long)(m0 + row) * Kd + kb + kc8 * 8;
                sal = Al + (long long)(m0 + row) * Kd + kb + kc8 * 8;
            }
            const __half* sbh = Bh + (long long)(n0 + row) * Kd + kb + kc8 * 8;
            const __half* sbl = Bl + (long long)(n0 + row) * Kd + kb + kc8 * 8;
            cp16(sb + doff,             sa);
            cp16(sb + 16384 + doff,     sal);
            cp16(sb + 32768 + doff,     sbh);
            cp16(sb + 49152 + doff,     sbl);
        }
    };

    float acc[4][4][4];
    #pragma unroll
    for (int i = 0; i < 4; i++)
        #pragma unroll
        for (int j = 0; j < 4; j++)
            #pragma unroll
            for (int r = 0; r < 4; r++) acc[i][j][r] = 0.0f;

    issue(0, 0); CP_COMMIT();
    issue(1, 1); CP_COMMIT();
    issue(2, 2); CP_COMMIT();

    const int arow_l = wm * 64 + (lane & 15);
    const int akch   = (lane >> 4) << 4;
    const int brow_l = wn * 32 + ((lane >> 4) << 3) + (lane & 7);
    const int bkch   = ((lane >> 3) & 1) << 4;

    for (int it = 0; it < nIter; it++) {
        const int st = it - (it / 3) * 3;
        CP_WAIT2();
        __syncthreads();

        const uint32_t sb = sm0 + st * STAGE_BYTES;
        #pragma unroll
        for (int kc = 0; kc < 4; kc++) {
            uint32_t ah[4][4], al[4][4], bh[2][4], bl[2][4];
            #pragma unroll
            for (int mf = 0; mf < 4; mf++) {
                int row = arow_l + mf * 16;
                uint32_t addr = sb + row * 128 + ((kc * 32 + akch) ^ ((row & 7) << 4));
                ldsm4(ah[mf], addr);
                ldsm4(al[mf], addr + 16384);
            }
            #pragma unroll
            for (int ng = 0; ng < 2; ng++) {
                int row = brow_l + ng * 16;
                uint32_t addr = sb + 32768 + row * 128 +
                                ((kc * 32 + bkch) ^ ((row & 7) << 4));
                ldsm4(bh[ng], addr);
                ldsm4(bl[ng], addr + 16384);
            }
            // Pass-outermost ordering: every consecutive MMA hits a different
            // accumulator (16 apart before reuse) — no dependent HMMA chains.
            #pragma unroll
            for (int mf = 0; mf < 4; mf++)
                #pragma unroll
                for (int nf = 0; nf < 4; nf++) {
                    const int ng = nf >> 1, j = nf & 1;
                    mma16816(acc[mf][nf], ah[mf], bh[ng][2 * j], bh[ng][2 * j + 1]);
                }
            #pragma unroll
            for (int mf = 0; mf < 4; mf++)
                #pragma unroll
                for (int nf = 0; nf < 4; nf++) {
                    const int ng = nf >> 1, j = nf & 1;
                    mma16816(acc[mf][nf], al[mf], bh[ng][2 * j], bh[ng][2 * j + 1]);
                }
            #pragma unroll
            for (int mf = 0; mf < 4; mf++)
                #pragma unroll
                for (int nf = 0; nf < 4; nf++) {
                    const int ng = nf >> 1, j = nf & 1;
                    mma16816(acc[mf][nf], ah[mf], bl[ng][2 * j], bl[ng][2 * j + 1]);
                }
        }
        __syncthreads();
        if (it + 3 < nIter) issue(it + 3, st);
        CP_COMMIT();
    }

    // ---- epilogue ----
    const int g   = lane >> 2;
    const int cp2 = (lane & 3) * 2;
    #pragma unroll
    for (int mf = 0; mf < 4; mf++) {
        #pragma unroll
        for (int nf = 0; nf < 4; nf++) {
            int row0 = m0 + wm * 64 + mf * 16 + g;
            int row1 = row0 + 8;
            int col  = n0 + wn * 32 + nf * 8 + cp2;
            float v00 = acc[mf][nf][0] * alpha;
            float v01 = acc[mf][nf][1] * alpha;
            float v10 = acc[mf][nf][2] * alpha;
            float v11 = acc[mf][nf][3] * alpha;
            if (bptr) {
                float b0 = bptr[col], b1 = bptr[col + 1];
                v00 += b0; v01 += b1; v10 += b0; v11 += b1;
            }
            if (EPI == 0) {
                *reinterpret_cast<float2*>(Cf + coff + (long long)row0 * Nd + col) =
                    make_float2(v00, v01);
                *reinterpret_cast<float2*>(Cf + coff + (long long)row1 * Nd + col) =
                    make_float2(v10, v11);
            } else if (EPI == 1) {
                __half h00, l00, h01, l01, h10, l10, h11, l11;
                split(v00, h00, l00); split(v01, h01, l01);
                split(v10, h10, l10); split(v11, h11, l11);
                __half2 hh0; hh0.x = h00; hh0.y = h01;
                __half2 ll0; ll0.x = l00; ll0.y = l01;
                __half2 hh1; hh1.x = h10; hh1.y = h11;
                __half2 ll1; ll1.x = l10; ll1.y = l11;
                *reinterpret_cast<__half2*>(Ch + coff + (long long)row0 * Nd + col) = hh0;
                *reinterpret_cast<__half2*>(Cl + coff + (long long)row0 * Nd + col) = ll0;
                *reinterpret_cast<__half2*>(Ch + coff + (long long)row1 * Nd + col) = hh1;
                *reinterpret_cast<__half2*>(Cl + coff + (long long)row1 * Nd + col) = ll1;
            } else {
                __half h, l;
                split(v00, h, l);
                Ch[coff + (long long)col * Md + row0] = h;
                Cl[coff + (long long)col * Md + row0] = l;
                split(v01, h, l);
                Ch[coff + (long long)(col + 1) * Md + row0] = h;
                Cl[coff + (long long)(col + 1) * Md + row0] = l;
                split(v10, h, l);
                Ch[coff + (long long)col * Md + row1] = h;
                Cl[coff + (long long)col * Md + row1] = l;
                split(v11, h, l);
                Ch[coff + (long long)(col + 1) * Md + row1] = h;
                Cl[coff + (long long)(col + 1) * Md + row1] = l;
            }
        }
    }
}

// -------------------------------------------------------------------------
// fp32 -> fp16 hi/lo split (elementwise)
// -------------------------------------------------------------------------
__global__ void __launch_bounds__(256) convsplit_kernel(
    const float* __restrict__ src, __half* __restrict__ hi,
    __half* __restrict__ lo, size_t n4)
{
    size_t i = (size_t)blockIdx.x * 256 + threadIdx.x;
    if (i >= n4) return;
    float4 v = reinterpret_cast<const float4*>(src)[i];
    __half h0, l0, h1, l1, h2, l2, h3, l3;
    split(v.x, h0, l0); split(v.y, h1, l1);
    split(v.z, h2, l2); split(v.w, h3, l3);
    __half2 ha; ha.x = h0; ha.y = h1;
    __half2 hb; hb.x = h2; hb.y = h3;
    __half2 la; la.x = l0; la.y = l1;
    __half2 lb; lb.x = l2; lb.y = l3;
    reinterpret_cast<__half2*>(hi)[2 * i]     = ha;
    reinterpret_cast<__half2*>(hi)[2 * i + 1] = hb;
    reinterpret_cast<__half2*>(lo)[2 * i]     = la;
    reinterpret_cast<__half2*>(lo)[2 * i + 1] = lb;
}

// -------------------------------------------------------------------------
// Batched transpose + split: dst_hi/lo[z][c][r] = split(src[z][r][c])
// -------------------------------------------------------------------------
__global__ void __launch_bounds__(256) transpose_split_kernel(
    const float* __restrict__ src, __half* __restrict__ hi,
    __half* __restrict__ lo, int R, int C)
{
    __shared__ float t[32][33];
    const size_t zoff = (size_t)blockIdx.z * R * C;
    int tx = threadIdx.x, ty = threadIdx.y;
    int x = blockIdx.x * 32 + tx;
    int y = blockIdx.y * 32 + ty;
    #pragma unroll
    for (int j = 0; j < 32; j += 8)
        t[ty + j][tx] = src[zoff + (size_t)(y + j) * C + x];
    __syncthreads();
    int x2 = blockIdx.y * 32 + tx;
    int y2 = blockIdx.x * 32 + ty;
    #pragma unroll
    for (int j = 0; j < 32; j += 8) {
        float v = t[tx][ty + j];
        __half h, l;
        split(v, h, l);
        hi[zoff + (size_t)(y2 + j) * R + x2] = h;
        lo[zoff + (size_t)(y2 + j) * R + x2] = l;
    }
}

// -------------------------------------------------------------------------
// Wo permute+transpose+split: WoP[k = h*512+d][n] holds Wo[d*8+h][n],
// stored as [k][n]?  No — B operand layout is [Nd][Kd] K-major:
//   WoP_B[n][k] = Wo[(k&511)*8 + (k>>9)][n]
// One block per output n-row (512 rows), 4096 k per row; reads of Wo are
// strided but per-warp contiguous in n... simpler: block per k-row of a
// [Kd][Nd] staging view is wrong; do it directly per (n-block, k-block).
// Each thread: out[n][k], read Wo[(k&511)*8 + (k>>9)][n] (column read,
// coalesced along n for fixed k? no — out is k-contiguous).
// Use tile transpose: load Wo tile rows (d*8+h fixed h), write out rows n.
// -------------------------------------------------------------------------
__global__ void __launch_bounds__(256) wo_permute_split_kernel(
    const float* __restrict__ Wo, __half* __restrict__ hi, __half* __restrict__ lo)
{
    // tile: 32 k-values (same h) x 32 n-values
    __shared__ float t[32][33];
    int tx = threadIdx.x, ty = threadIdx.y;       // 32 x 8
    int kb = blockIdx.x * 32;                      // k block (within h: contiguous d)
    int nb = blockIdx.y * 32;
    int h  = kb >> 9;
    int d0 = kb & 511;
    // load: t[i][j] = Wo[(d0+i)*8 + h][nb + j]  (coalesced along n = tx)
    #pragma unroll
    for (int j = 0; j < 32; j += 8) {
        int d = d0 + ty + j;
        t[ty + j][tx] = Wo[(size_t)(d * 8 + h) * D_ + nb + tx];
    }
    __syncthreads();
    // write: out[n = nb+i][k = kb+j] = t[j][i]  (coalesced along k = tx)
    #pragma unroll
    for (int j = 0; j < 32; j += 8) {
        int n = nb + ty + j;
        float v = t[tx][ty + j];
        __half hh, ll;
        split(v, hh, ll);
        hi[(size_t)n * HD_ + kb + tx] = hh;
        lo[(size_t)n * HD_ + kb + tx] = ll;
    }
}

// -------------------------------------------------------------------------
// Row softmax over N_=2048, emits fp16 hi/lo probability arrays.
// -------------------------------------------------------------------------
__global__ void __launch_bounds__(256) softmax_kernel(
    const float* __restrict__ S, __half* __restrict__ Ph, __half* __restrict__ Pl)
{
    const long long roff = (long long)blockIdx.x * N_;
    const float* p = S + roff;
    const int tid = threadIdx.x;

    float4 v0 = *reinterpret_cast<const float4*>(p + tid * 8);
    float4 v1 = *reinterpret_cast<const float4*>(p + tid * 8 + 4);

    float m = fmaxf(fmaxf(fmaxf(v0.x, v0.y), fmaxf(v0.z, v0.w)),
                    fmaxf(fmaxf(v1.x, v1.y), fmaxf(v1.z, v1.w)));
    #pragma unroll
    for (int o = 16; o > 0; o >>= 1)
        m = fmaxf(m, __shfl_xor_sync(0xffffffffu, m, o));

    __shared__ float smax[8];
    __shared__ float ssum[8];
    if ((tid & 31) == 0) smax[tid >> 5] = m;
    __syncthreads();
    m = smax[0];
    #pragma unroll
    for (int i = 1; i < 8; i++) m = fmaxf(m, smax[i]);

    v0.x = __expf(v0.x - m); v0.y = __expf(v0.y - m);
    v0.z = __expf(v0.z - m); v0.w = __expf(v0.w - m);
    v1.x = __expf(v1.x - m); v1.y = __expf(v1.y - m);
    v1.z = __expf(v1.z - m); v1.w = __expf(v1.w - m);

    float s = v0.x + v0.y + v0.z + v0.w + v1.x + v1.y + v1.z + v1.w;
    #pragma unroll
    for (int o = 16; o > 0; o >>= 1)
        s += __shfl_xor_sync(0xffffffffu, s, o);
    if ((tid & 31) == 0) ssum[tid >> 5] = s;
    __syncthreads();
    s = 0.0f;
    #pragma unroll
    for (int i = 0; i < 8; i++) s += ssum[i];

    const float inv = 1.0f / s;
    float pv[8] = { v0.x * inv, v0.y * inv, v0.z * inv, v0.w * inv,
                    v1.x * inv, v1.y * inv, v1.z * inv, v1.w * inv };
    __half2 hh[4], ll[4];
    #pragma unroll
    for (int i = 0; i < 4; i++) {
        __half h0, l0, h1, l1;
        split(pv[2 * i], h0, l0);
        split(pv[2 * i + 1], h1, l1);
        hh[i].x = h0; hh[i].y = h1;
        ll[i].x = l0; ll[i].y = l1;
    }
    *reinterpret_cast<uint4*>(Ph + roff + tid * 8) = *reinterpret_cast<uint4*>(hh);
    *reinterpret_cast<uint4*>(Pl + roff + tid * 8) = *reinterpret_cast<uint4*>(ll);
}

// -------------------------------------------------------------------------
// Launch
// -------------------------------------------------------------------------
extern "C" void kernel_launch(void* const* d_in, const int* in_sizes, int n_in,
                              void* d_out, int out_size)
{
    (void)in_sizes; (void)n_in; (void)out_size;
    const float* k  = (const float*)d_in[0];
    const float* v  = (const float*)d_in[1];
    const float* q  = (const float*)d_in[2];
    const float* Wk = (const float*)d_in[3];
    const float* bk = (const float*)d_in[4];
    const float* Wv = (const float*)d_in[5];
    const float* bv = (const float*)d_in[6];
    const float* Wq = (const float*)d_in[7];
    const float* bq = (const float*)d_in[8];
    const float* Wo = (const float*)d_in[9];
    const float* bo = (const float*)d_in[10];
    float* out = (float*)d_out;

    __half *kc_hi, *kc_lo, *vc_hi, *vc_lo, *qc_hi, *qc_lo;
    __half *WkT_hi, *WkT_lo, *WvT_hi, *WvT_lo, *WqT_hi, *WqT_lo, *WoP_hi, *WoP_lo;
    __half *kp_hi, *kp_lo, *qp_hi, *qp_lo, *vT_hi, *vT_lo;
    __half *P_hi, *P_lo, *at_hi, *at_lo;
    float *sc;
    cudaGetSymbolAddress((void**)&kc_hi, g_kc_hi);  cudaGetSymbolAddress((void**)&kc_lo, g_kc_lo);
    cudaGetSymbolAddress((void**)&vc_hi, g_vc_hi);  cudaGetSymbolAddress((void**)&vc_lo, g_vc_lo);
    cudaGetSymbolAddress((void**)&qc_hi, g_qc_hi);  cudaGetSymbolAddress((void**)&qc_lo, g_qc_lo);
    cudaGetSymbolAddress((void**)&WkT_hi, g_WkT_hi); cudaGetSymbolAddress((void**)&WkT_lo, g_WkT_lo);
    cudaGetSymbolAddress((void**)&WvT_hi, g_WvT_hi); cudaGetSymbolAddress((void**)&WvT_lo, g_WvT_lo);
    cudaGetSymbolAddress((void**)&WqT_hi, g_WqT_hi); cudaGetSymbolAddress((void**)&WqT_lo, g_WqT_lo);
    cudaGetSymbolAddress((void**)&WoP_hi, g_WoP_hi); cudaGetSymbolAddress((void**)&WoP_lo, g_WoP_lo);
    cudaGetSymbolAddress((void**)&kp_hi, g_kp_hi);  cudaGetSymbolAddress((void**)&kp_lo, g_kp_lo);
    cudaGetSymbolAddress((void**)&qp_hi, g_qp_hi);  cudaGetSymbolAddress((void**)&qp_lo, g_qp_lo);
    cudaGetSymbolAddress((void**)&vT_hi, g_vT_hi);  cudaGetSymbolAddress((void**)&vT_lo, g_vT_lo);
    cudaGetSymbolAddress((void**)&P_hi, g_P_hi);    cudaGetSymbolAddress((void**)&P_lo, g_P_lo);
    cudaGetSymbolAddress((void**)&at_hi, g_at_hi);  cudaGetSymbolAddress((void**)&at_lo, g_at_lo);
    cudaGetSymbolAddress((void**)&sc, g_scores);

    const long long sND = (long long)N_ * D_;
    const long long sDD = (long long)D_ * D_;
    const long long sMN = (long long)M_ * N_;
    const long long sMH = (long long)M_ * HD_;
    const long long sMD = (long long)M_ * D_;
    const long long sAB = (long long)H_ * M_ * D_;   // attn batch stride

    cudaFuncSetAttribute(hgemm_kernel<0, false>, cudaFuncAttributeMaxDynamicSharedMemorySize, SHM_TOTAL);
    cudaFuncSetAttribute(hgemm_kernel<1, false>, cudaFuncAttributeMaxDynamicSharedMemorySize, SHM_TOTAL);
    cudaFuncSetAttribute(hgemm_kernel<2, false>, cudaFuncAttributeMaxDynamicSharedMemorySize, SHM_TOTAL);
    cudaFuncSetAttribute(hgemm_kernel<0, true>,  cudaFuncAttributeMaxDynamicSharedMemorySize, SHM_TOTAL);

    // 0) split inputs, transpose+split weights, permute Wo
    {
        size_t n4 = (size_t)B_ * N_ * D_ / 4;
        int gb = (int)((n4 + 255) / 256);
        convsplit_kernel<<<gb, 256>>>(k, kc_hi, kc_lo, n4);
        convsplit_kernel<<<gb, 256>>>(v, vc_hi, vc_lo, n4);
        convsplit_kernel<<<gb, 256>>>(q, qc_hi, qc_lo, n4);
        dim3 tb(32, 8);
        transpose_split_kernel<<<dim3(D_ / 32, D_ / 32, H_), tb>>>(Wk, WkT_hi, WkT_lo, D_, D_);
        transpose_split_kernel<<<dim3(D_ / 32, D_ / 32, H_), tb>>>(Wv, WvT_hi, WvT_lo, D_, D_);
        transpose_split_kernel<<<dim3(D_ / 32, D_ / 32, H_), tb>>>(Wq, WqT_hi, WqT_lo, D_, D_);
        wo_permute_split_kernel<<<dim3(HD_ / 32, D_ / 32), tb>>>(Wo, WoP_hi, WoP_lo);
    }

    // 1) projections
    {
        dim3 grid(D_ / 128, N_ / 128, BH_);
        hgemm_kernel<1, false><<<grid, 256, SHM_TOTAL>>>(kc_hi, kc_lo, WkT_hi, WkT_lo,
            nullptr, kp_hi, kp_lo, N_, D_, D_, H_, H_, sND, sDD, sND, 1.0f, bk, D_);
        hgemm_kernel<1, false><<<grid, 256, SHM_TOTAL>>>(qc_hi, qc_lo, WqT_hi, WqT_lo,
            nullptr, qp_hi, qp_lo, M_, D_, D_, H_, H_, sND, sDD, sND, 1.0f, bq, D_);
        hgemm_kernel<2, false><<<grid, 256, SHM_TOTAL>>>(vc_hi, vc_lo, WvT_hi, WvT_lo,
            nullptr, vT_hi, vT_lo, N_, D_, D_, H_, H_, sND, sDD, sND, 1.0f, bv, D_);
    }

    // 2) scores = (q' @ k'^T) / sqrt(D)
    {
        dim3 grid(N_ / 128, M_ / 128, BH_);
        const float scale = 0.044194173824159216f;
        hgemm_kernel<0, false><<<grid, 256, SHM_TOTAL>>>(qp_hi, qp_lo, kp_hi, kp_lo,
            sc, nullptr, nullptr, M_, N_, D_, 1, BH_, sMD, sND, sMN, scale, nullptr, 0);
    }

    // 3) softmax -> P hi/lo
    softmax_kernel<<<BH_ * M_, 256>>>(sc, P_hi, P_lo);

    // 4) attn = P @ v'  -> fp16 hi/lo, layout [z][m][d]
    {
        dim3 grid(D_ / 128, M_ / 128, BH_);
        hgemm_kernel<1, false><<<grid, 256, SHM_TOTAL>>>(P_hi, P_lo, vT_hi, vT_lo,
            nullptr, at_hi, at_lo, M_, D_, N_, 1, BH_, sMN, sND, sMD, 1.0f, nullptr, 0);
    }

    // 5) out = attn(gathered, k = h*512+d) @ WoP + bo
    {
        dim3 grid(D_ / 128, M_ / 128, B_);
        hgemm_kernel<0, true><<<grid, 256, SHM_TOTAL>>>(at_hi, at_lo, WoP_hi, WoP_lo,
            out, nullptr, nullptr, M_, D_, HD_, 1, 1, sAB, 0, sMD, 1.0f, bo, 0);
    }
}

// round 8
// speedup vs baseline: 3.9640x; 1.3219x over previous
#include <cuda_runtime.h>
#include <cuda_fp16.h>
#include <cstdint>

#define B_  8
#define N_  2048
#define M_  2048
#define D_  512
#define H_  8
#define BH_ (B_ * H_)
#define HD_ (H_ * D_)

// -------------------------------------------------------------------------
// Device scratch.  A-side operands keep fp16 hi/lo pairs (full precision);
// B-side operands are fp16 hi only (2-pass split scheme).
// -------------------------------------------------------------------------
__device__ __half g_kc_hi[(size_t)B_ * N_ * D_], g_kc_lo[(size_t)B_ * N_ * D_];
__device__ __half g_vc_hi[(size_t)B_ * N_ * D_], g_vc_lo[(size_t)B_ * N_ * D_];
__device__ __half g_qc_hi[(size_t)B_ * M_ * D_], g_qc_lo[(size_t)B_ * M_ * D_];
__device__ __half g_WkT_hi[(size_t)H_ * D_ * D_];
__device__ __half g_WvT_hi[(size_t)H_ * D_ * D_];
__device__ __half g_WqT_hi[(size_t)H_ * D_ * D_];
__device__ __half g_WoP_hi[(size_t)D_ * HD_];                  // [n=512][k=h*512+d]
__device__ __half g_kp_hi[(size_t)BH_ * N_ * D_];              // k' (B operand only)
__device__ __half g_qp_hi[(size_t)BH_ * M_ * D_], g_qp_lo[(size_t)BH_ * M_ * D_];
__device__ __half g_vT_hi[(size_t)BH_ * D_ * N_];              // v'^T (B operand only)
__device__ float  g_scores[(size_t)BH_ * M_ * N_];
__device__ __half g_P_hi[(size_t)BH_ * M_ * N_],  g_P_lo[(size_t)BH_ * M_ * N_];
__device__ __half g_at_hi[(size_t)BH_ * M_ * D_], g_at_lo[(size_t)BH_ * M_ * D_];

// -------------------------------------------------------------------------
// PTX helpers (family-baseline instructions only)
// -------------------------------------------------------------------------
__device__ __forceinline__ uint32_t smem_to_u32(const void* p) {
    uint32_t a;
    asm("{ .reg .u64 t; cvta.to.shared.u64 t, %1; cvt.u32.u64 %0, t; }" : "=r"(a) : "l"(p));
    return a;
}
__device__ __forceinline__ void cp16(uint32_t dst, const void* src) {
    asm volatile("cp.async.cg.shared.global [%0], [%1], 16;" :: "r"(dst), "l"(src));
}
#define CP_COMMIT() asm volatile("cp.async.commit_group;" ::: "memory")
#define CP_WAIT2()  asm volatile("cp.async.wait_group 2;" ::: "memory")

__device__ __forceinline__ void ldsm4(uint32_t* r, uint32_t addr) {
    asm volatile("ldmatrix.sync.aligned.m8n8.x4.shared.b16 {%0,%1,%2,%3}, [%4];"
                 : "=r"(r[0]), "=r"(r[1]), "=r"(r[2]), "=r"(r[3]) : "r"(addr));
}
__device__ __forceinline__ void mma16816(float* c, const uint32_t* a,
                                         uint32_t b0, uint32_t b1) {
    asm volatile("mma.sync.aligned.m16n8k16.row.col.f32.f16.f16.f32 "
                 "{%0,%1,%2,%3}, {%4,%5,%6,%7}, {%8,%9}, {%0,%1,%2,%3};"
                 : "+f"(c[0]), "+f"(c[1]), "+f"(c[2]), "+f"(c[3])
                 : "r"(a[0]), "r"(a[1]), "r"(a[2]), "r"(a[3]), "r"(b0), "r"(b1));
}
__device__ __forceinline__ void split(float v, __half& h, __half& l) {
    h = __float2half_rn(v);
    l = __float2half_rn(v - __half2float(h));
}

// -------------------------------------------------------------------------
// 2-pass fp16 tensor-core GEMM.  C[z] = alpha * A[z] @ B[z]^T (+ bias)
// A: [Md, Kd] fp16 hi/lo row-major (full precision).
// B: [Nd, Kd] fp16 hi only, K-major.
// Passes: A_hi*B_hi + A_lo*B_hi.
// EPI: 0 = fp32 out; 1 = fp16 hi/lo pair out; 2 = fp16 hi transposed out;
//      3 = fp16 hi out (row-major).
// GA:  gather A from attention layout [h][m][d], k = h*512 + d.
// CTA 128x128, BK=64, 256 threads (2x4 warps), 3-stage cp.async pipeline.
// Stage = A_hi(16K) + A_lo(16K) + B_hi(16K) = 48KB.
// -------------------------------------------------------------------------
#define STAGE_BYTES 49152
#define SHM_TOTAL   (3 * STAGE_BYTES)

template <int EPI, bool GA>
__global__ void __launch_bounds__(256, 1) hgemm_kernel(
    const __half* __restrict__ Ah, const __half* __restrict__ Al,
    const __half* __restrict__ Bh,
    float* __restrict__ Cf, __half* __restrict__ Ch, __half* __restrict__ Cl,
    int Md, int Nd, int Kd, int divA, int modB,
    long long strideA, long long strideB, long long strideC,
    float alpha, const float* __restrict__ bias, int biasStride)
{
    extern __shared__ char smem[];
    const uint32_t sm0 = smem_to_u32(smem);
    const int tid = threadIdx.x;
    const int wid = tid >> 5, lane = tid & 31;
    const int wm = wid >> 2, wn = wid & 3;      // 2 x 4 warp grid

    const int z = blockIdx.z;
    Ah += (long long)(z / divA) * strideA;
    Al += (long long)(z / divA) * strideA;
    Bh += (long long)(z % modB) * strideB;
    const long long coff = (long long)z * strideC;
    const float* bptr = bias ? (bias + (long long)(z % modB) * biasStride) : nullptr;
    const int m0 = blockIdx.y * 128;
    const int n0 = blockIdx.x * 128;

    const int nIter = Kd >> 6;

    // ---- cp.async stage issue: A_hi, A_lo, B_hi ----
    auto issue = [&](int it, int st) {
        const uint32_t sb = sm0 + st * STAGE_BYTES;
        const int kb = it * 64;
        const long long ga_off = GA ? ((long long)(kb >> 9) * ((long long)M_ * D_) + (kb & 511))
                                    : 0;
        #pragma unroll
        for (int i = 0; i < 4; i++) {
            int ci = tid + i * 256;          // 0..1023
            int row = ci >> 3;               // 0..127
            int kc8 = ci & 7;                // 16B chunk within 128B row
            uint32_t doff = row * 128 + ((kc8 * 16) ^ ((row & 7) << 4));
            const __half *sa, *sal;
            if (GA) {
                sa  = Ah + ga_off + (long long)(m0 + row) * D_ + kc8 * 8;
                sal = Al + ga_off + (long long)(m0 + row) * D_ + kc8 * 8;
            } else {
                sa  = Ah + (long long)(m0 + row) * Kd + kb + kc8 * 8;
                sal = Al + (long long)(m0 + row) * Kd + kb + kc8 * 8;
            }
            const __half* sbh = Bh + (long long)(n0 + row) * Kd + kb + kc8 * 8;
            cp16(sb + doff,             sa);
            cp16(sb + 16384 + doff,     sal);
            cp16(sb + 32768 + doff,     sbh);
        }
    };

    float acc[4][4][4];
    #pragma unroll
    for (int i = 0; i < 4; i++)
        #pragma unroll
        for (int j = 0; j < 4; j++)
            #pragma unroll
            for (int r = 0; r < 4; r++) acc[i][j][r] = 0.0f;

    issue(0, 0); CP_COMMIT();
    issue(1, 1); CP_COMMIT();
    issue(2, 2); CP_COMMIT();

    const int arow_l = wm * 64 + (lane & 15);
    const int akch   = (lane >> 4) << 4;
    const int brow_l = wn * 32 + ((lane >> 4) << 3) + (lane & 7);
    const int bkch   = ((lane >> 3) & 1) << 4;

    for (int it = 0; it < nIter; it++) {
        const int st = it - (it / 3) * 3;
        CP_WAIT2();
        __syncthreads();

        const uint32_t sb = sm0 + st * STAGE_BYTES;
        #pragma unroll
        for (int kc = 0; kc < 4; kc++) {
            uint32_t ah[4][4], al[4][4], bh[2][4];
            #pragma unroll
            for (int mf = 0; mf < 4; mf++) {
                int row = arow_l + mf * 16;
                uint32_t addr = sb + row * 128 + ((kc * 32 + akch) ^ ((row & 7) << 4));
                ldsm4(ah[mf], addr);
                ldsm4(al[mf], addr + 16384);
            }
            #pragma unroll
            for (int ng = 0; ng < 2; ng++) {
                int row = brow_l + ng * 16;
                uint32_t addr = sb + 32768 + row * 128 +
                                ((kc * 32 + bkch) ^ ((row & 7) << 4));
                ldsm4(bh[ng], addr);
            }
            #pragma unroll
            for (int mf = 0; mf < 4; mf++)
                #pragma unroll
                for (int nf = 0; nf < 4; nf++) {
                    const int ng = nf >> 1, j = nf & 1;
                    mma16816(acc[mf][nf], ah[mf], bh[ng][2 * j], bh[ng][2 * j + 1]);
                }
            #pragma unroll
            for (int mf = 0; mf < 4; mf++)
                #pragma unroll
                for (int nf = 0; nf < 4; nf++) {
                    const int ng = nf >> 1, j = nf & 1;
                    mma16816(acc[mf][nf], al[mf], bh[ng][2 * j], bh[ng][2 * j + 1]);
                }
        }
        __syncthreads();
        if (it + 3 < nIter) issue(it + 3, st);
        CP_COMMIT();
    }

    // ---- epilogue ----
    const int g   = lane >> 2;
    const int cp2 = (lane & 3) * 2;
    #pragma unroll
    for (int mf = 0; mf < 4; mf++) {
        #pragma unroll
        for (int nf = 0; nf < 4; nf++) {
            int row0 = m0 + wm * 64 + mf * 16 + g;
            int row1 = row0 + 8;
            int col  = n0 + wn * 32 + nf * 8 + cp2;
            float v00 = acc[mf][nf][0] * alpha;
            float v01 = acc[mf][nf][1] * alpha;
            float v10 = acc[mf][nf][2] * alpha;
            float v11 = acc[mf][nf][3] * alpha;
            if (bptr) {
                float b0 = bptr[col], b1 = bptr[col + 1];
                v00 += b0; v01 += b1; v10 += b0; v11 += b1;
            }
            if (EPI == 0) {
                *reinterpret_cast<float2*>(Cf + coff + (long long)row0 * Nd + col) =
                    make_float2(v00, v01);
                *reinterpret_cast<float2*>(Cf + coff + (long long)row1 * Nd + col) =
                    make_float2(v10, v11);
            } else if (EPI == 1) {
                __half h00, l00, h01, l01, h10, l10, h11, l11;
                split(v00, h00, l00); split(v01, h01, l01);
                split(v10, h10, l10); split(v11, h11, l11);
                __half2 hh0; hh0.x = h00; hh0.y = h01;
                __half2 ll0; ll0.x = l00; ll0.y = l01;
                __half2 hh1; hh1.x = h10; hh1.y = h11;
                __half2 ll1; ll1.x = l10; ll1.y = l11;
                *reinterpret_cast<__half2*>(Ch + coff + (long long)row0 * Nd + col) = hh0;
                *reinterpret_cast<__half2*>(Cl + coff + (long long)row0 * Nd + col) = ll0;
                *reinterpret_cast<__half2*>(Ch + coff + (long long)row1 * Nd + col) = hh1;
                *reinterpret_cast<__half2*>(Cl + coff + (long long)row1 * Nd + col) = ll1;
            } else if (EPI == 2) {
                Ch[coff + (long long)col * Md + row0]       = __float2half_rn(v00);
                Ch[coff + (long long)(col + 1) * Md + row0] = __float2half_rn(v01);
                Ch[coff + (long long)col * Md + row1]       = __float2half_rn(v10);
                Cl == nullptr ? void(0) : void(0);
                Ch[coff + (long long)(col + 1) * Md + row1] = __float2half_rn(v11);
            } else {  // EPI == 3: hi only, row-major
                __half2 hh0; hh0.x = __float2half_rn(v00); hh0.y = __float2half_rn(v01);
                __half2 hh1; hh1.x = __float2half_rn(v10); hh1.y = __float2half_rn(v11);
                *reinterpret_cast<__half2*>(Ch + coff + (long long)row0 * Nd + col) = hh0;
                *reinterpret_cast<__half2*>(Ch + coff + (long long)row1 * Nd + col) = hh1;
            }
        }
    }
}

// -------------------------------------------------------------------------
// fp32 -> fp16 hi/lo split (elementwise)
// -------------------------------------------------------------------------
__global__ void __launch_bounds__(256) convsplit_kernel(
    const float* __restrict__ src, __half* __restrict__ hi,
    __half* __restrict__ lo, size_t n4)
{
    size_t i = (size_t)blockIdx.x * 256 + threadIdx.x;
    if (i >= n4) return;
    float4 v = reinterpret_cast<const float4*>(src)[i];
    __half h0, l0, h1, l1, h2, l2, h3, l3;
    split(v.x, h0, l0); split(v.y, h1, l1);
    split(v.z, h2, l2); split(v.w, h3, l3);
    __half2 ha; ha.x = h0; ha.y = h1;
    __half2 hb; hb.x = h2; hb.y = h3;
    __half2 la; la.x = l0; la.y = l1;
    __half2 lb; lb.x = l2; lb.y = l3;
    reinterpret_cast<__half2*>(hi)[2 * i]     = ha;
    reinterpret_cast<__half2*>(hi)[2 * i + 1] = hb;
    reinterpret_cast<__half2*>(lo)[2 * i]     = la;
    reinterpret_cast<__half2*>(lo)[2 * i + 1] = lb;
}

// -------------------------------------------------------------------------
// Batched transpose (hi only): dst[z][c][r] = fp16(src[z][r][c])
// -------------------------------------------------------------------------
__global__ void __launch_bounds__(256) transpose_h_kernel(
    const float* __restrict__ src, __half* __restrict__ hi, int R, int C)
{
    __shared__ float t[32][33];
    const size_t zoff = (size_t)blockIdx.z * R * C;
    int tx = threadIdx.x, ty = threadIdx.y;
    int x = blockIdx.x * 32 + tx;
    int y = blockIdx.y * 32 + ty;
    #pragma unroll
    for (int j = 0; j < 32; j += 8)
        t[ty + j][tx] = src[zoff + (size_t)(y + j) * C + x];
    __syncthreads();
    int x2 = blockIdx.y * 32 + tx;
    int y2 = blockIdx.x * 32 + ty;
    #pragma unroll
    for (int j = 0; j < 32; j += 8)
        hi[zoff + (size_t)(y2 + j) * R + x2] = __float2half_rn(t[tx][ty + j]);
}

// -------------------------------------------------------------------------
// Wo permute+transpose (hi only): out[n][k = h*512+d] = fp16(Wo[d*8+h][n])
// -------------------------------------------------------------------------
__global__ void __launch_bounds__(256) wo_permute_h_kernel(
    const float* __restrict__ Wo, __half* __restrict__ hi)
{
    __shared__ float t[32][33];
    int tx = threadIdx.x, ty = threadIdx.y;       // 32 x 8
    int kb = blockIdx.x * 32;
    int nb = blockIdx.y * 32;
    int h  = kb >> 9;
    int d0 = kb & 511;
    #pragma unroll
    for (int j = 0; j < 32; j += 8) {
        int d = d0 + ty + j;
        t[ty + j][tx] = Wo[(size_t)(d * 8 + h) * D_ + nb + tx];
    }
    __syncthreads();
    #pragma unroll
    for (int j = 0; j < 32; j += 8) {
        int n = nb + ty + j;
        hi[(size_t)n * HD_ + kb + tx] = __float2half_rn(t[tx][ty + j]);
    }
}

// -------------------------------------------------------------------------
// Row softmax over N_=2048, emits fp16 hi/lo probability arrays.
// -------------------------------------------------------------------------
__global__ void __launch_bounds__(256) softmax_kernel(
    const float* __restrict__ S, __half* __restrict__ Ph, __half* __restrict__ Pl)
{
    const long long roff = (long long)blockIdx.x * N_;
    const float* p = S + roff;
    const int tid = threadIdx.x;

    float4 v0 = *reinterpret_cast<const float4*>(p + tid * 8);
    float4 v1 = *reinterpret_cast<const float4*>(p + tid * 8 + 4);

    float m = fmaxf(fmaxf(fmaxf(v0.x, v0.y), fmaxf(v0.z, v0.w)),
                    fmaxf(fmaxf(v1.x, v1.y), fmaxf(v1.z, v1.w)));
    #pragma unroll
    for (int o = 16; o > 0; o >>= 1)
        m = fmaxf(m, __shfl_xor_sync(0xffffffffu, m, o));

    __shared__ float smax[8];
    __shared__ float ssum[8];
    if ((tid & 31) == 0) smax[tid >> 5] = m;
    __syncthreads();
    m = smax[0];
    #pragma unroll
    for (int i = 1; i < 8; i++) m = fmaxf(m, smax[i]);

    v0.x = __expf(v0.x - m); v0.y = __expf(v0.y - m);
    v0.z = __expf(v0.z - m); v0.w = __expf(v0.w - m);
    v1.x = __expf(v1.x - m); v1.y = __expf(v1.y - m);
    v1.z = __expf(v1.z - m); v1.w = __expf(v1.w - m);

    float s = v0.x + v0.y + v0.z + v0.w + v1.x + v1.y + v1.z + v1.w;
    #pragma unroll
    for (int o = 16; o > 0; o >>= 1)
        s += __shfl_xor_sync(0xffffffffu, s, o);
    if ((tid & 31) == 0) ssum[tid >> 5] = s;
    __syncthreads();
    s = 0.0f;
    #pragma unroll
    for (int i = 0; i < 8; i++) s += ssum[i];

    const float inv = 1.0f / s;
    float pv[8] = { v0.x * inv, v0.y * inv, v0.z * inv, v0.w * inv,
                    v1.x * inv, v1.y * inv, v1.z * inv, v1.w * inv };
    __half2 hh[4], ll[4];
    #pragma unroll
    for (int i = 0; i < 4; i++) {
        __half h0, l0, h1, l1;
        split(pv[2 * i], h0, l0);
        split(pv[2 * i + 1], h1, l1);
        hh[i].x = h0; hh[i].y = h1;
        ll[i].x = l0; ll[i].y = l1;
    }
    *reinterpret_cast<uint4*>(Ph + roff + tid * 8) = *reinterpret_cast<uint4*>(hh);
    *reinterpret_cast<uint4*>(Pl + roff + tid * 8) = *reinterpret_cast<uint4*>(ll);
}

// -------------------------------------------------------------------------
// Launch
// -------------------------------------------------------------------------
extern "C" void kernel_launch(void* const* d_in, const int* in_sizes, int n_in,
                              void* d_out, int out_size)
{
    (void)in_sizes; (void)n_in; (void)out_size;
    const float* k  = (const float*)d_in[0];
    const float* v  = (const float*)d_in[1];
    const float* q  = (const float*)d_in[2];
    const float* Wk = (const float*)d_in[3];
    const float* bk = (const float*)d_in[4];
    const float* Wv = (const float*)d_in[5];
    const float* bv = (const float*)d_in[6];
    const float* Wq = (const float*)d_in[7];
    const float* bq = (const float*)d_in[8];
    const float* Wo = (const float*)d_in[9];
    const float* bo = (const float*)d_in[10];
    float* out = (float*)d_out;

    __half *kc_hi, *kc_lo, *vc_hi, *vc_lo, *qc_hi, *qc_lo;
    __half *WkT_hi, *WvT_hi, *WqT_hi, *WoP_hi;
    __half *kp_hi, *qp_hi, *qp_lo, *vT_hi;
    __half *P_hi, *P_lo, *at_hi, *at_lo;
    float *sc;
    cudaGetSymbolAddress((void**)&kc_hi, g_kc_hi);  cudaGetSymbolAddress((void**)&kc_lo, g_kc_lo);
    cudaGetSymbolAddress((void**)&vc_hi, g_vc_hi);  cudaGetSymbolAddress((void**)&vc_lo, g_vc_lo);
    cudaGetSymbolAddress((void**)&qc_hi, g_qc_hi);  cudaGetSymbolAddress((void**)&qc_lo, g_qc_lo);
    cudaGetSymbolAddress((void**)&WkT_hi, g_WkT_hi);
    cudaGetSymbolAddress((void**)&WvT_hi, g_WvT_hi);
    cudaGetSymbolAddress((void**)&WqT_hi, g_WqT_hi);
    cudaGetSymbolAddress((void**)&WoP_hi, g_WoP_hi);
    cudaGetSymbolAddress((void**)&kp_hi, g_kp_hi);
    cudaGetSymbolAddress((void**)&qp_hi, g_qp_hi);  cudaGetSymbolAddress((void**)&qp_lo, g_qp_lo);
    cudaGetSymbolAddress((void**)&vT_hi, g_vT_hi);
    cudaGetSymbolAddress((void**)&P_hi, g_P_hi);    cudaGetSymbolAddress((void**)&P_lo, g_P_lo);
    cudaGetSymbolAddress((void**)&at_hi, g_at_hi);  cudaGetSymbolAddress((void**)&at_lo, g_at_lo);
    cudaGetSymbolAddress((void**)&sc, g_scores);

    const long long sND = (long long)N_ * D_;
    const long long sDD = (long long)D_ * D_;
    const long long sMN = (long long)M_ * N_;
    const long long sMD = (long long)M_ * D_;
    const long long sAB = (long long)H_ * M_ * D_;   // attn batch stride

    cudaFuncSetAttribute(hgemm_kernel<0, false>, cudaFuncAttributeMaxDynamicSharedMemorySize, SHM_TOTAL);
    cudaFuncSetAttribute(hgemm_kernel<1, false>, cudaFuncAttributeMaxDynamicSharedMemorySize, SHM_TOTAL);
    cudaFuncSetAttribute(hgemm_kernel<2, false>, cudaFuncAttributeMaxDynamicSharedMemorySize, SHM_TOTAL);
    cudaFuncSetAttribute(hgemm_kernel<3, false>, cudaFuncAttributeMaxDynamicSharedMemorySize, SHM_TOTAL);
    cudaFuncSetAttribute(hgemm_kernel<0, true>,  cudaFuncAttributeMaxDynamicSharedMemorySize, SHM_TOTAL);

    // 0) split inputs, convert weights (hi only)
    {
        size_t n4 = (size_t)B_ * N_ * D_ / 4;
        int gb = (int)((n4 + 255) / 256);
        convsplit_kernel<<<gb, 256>>>(k, kc_hi, kc_lo, n4);
        convsplit_kernel<<<gb, 256>>>(v, vc_hi, vc_lo, n4);
        convsplit_kernel<<<gb, 256>>>(q, qc_hi, qc_lo, n4);
        dim3 tb(32, 8);
        transpose_h_kernel<<<dim3(D_ / 32, D_ / 32, H_), tb>>>(Wk, WkT_hi, D_, D_);
        transpose_h_kernel<<<dim3(D_ / 32, D_ / 32, H_), tb>>>(Wv, WvT_hi, D_, D_);
        transpose_h_kernel<<<dim3(D_ / 32, D_ / 32, H_), tb>>>(Wq, WqT_hi, D_, D_);
        wo_permute_h_kernel<<<dim3(HD_ / 32, D_ / 32), tb>>>(Wo, WoP_hi);
    }

    // 1) projections: k' hi-only, q' pair, v' hi-only transposed
    {
        dim3 grid(D_ / 128, N_ / 128, BH_);
        hgemm_kernel<3, false><<<grid, 256, SHM_TOTAL>>>(kc_hi, kc_lo, WkT_hi,
            nullptr, kp_hi, nullptr, N_, D_, D_, H_, H_, sND, sDD, sND, 1.0f, bk, D_);
        hgemm_kernel<1, false><<<grid, 256, SHM_TOTAL>>>(qc_hi, qc_lo, WqT_hi,
            nullptr, qp_hi, qp_lo, M_, D_, D_, H_, H_, sND, sDD, sND, 1.0f, bq, D_);
        hgemm_kernel<2, false><<<grid, 256, SHM_TOTAL>>>(vc_hi, vc_lo, WvT_hi,
            nullptr, vT_hi, nullptr, N_, D_, D_, H_, H_, sND, sDD, sND, 1.0f, bv, D_);
    }

    // 2) scores = (q' @ k'^T) / sqrt(D)
    {
        dim3 grid(N_ / 128, M_ / 128, BH_);
        const float scale = 0.044194173824159216f;
        hgemm_kernel<0, false><<<grid, 256, SHM_TOTAL>>>(qp_hi, qp_lo, kp_hi,
            sc, nullptr, nullptr, M_, N_, D_, 1, BH_, sMD, sND, sMN, scale, nullptr, 0);
    }

    // 3) softmax -> P hi/lo
    softmax_kernel<<<BH_ * M_, 256>>>(sc, P_hi, P_lo);

    // 4) attn = P @ v'  -> fp16 hi/lo, layout [z][m][d]
    {
        dim3 grid(D_ / 128, M_ / 128, BH_);
        hgemm_kernel<1, false><<<grid, 256, SHM_TOTAL>>>(P_hi, P_lo, vT_hi,
            nullptr, at_hi, at_lo, M_, D_, N_, 1, BH_, sMN, sND, sMD, 1.0f, nullptr, 0);
    }

    // 5) out = attn(gathered, k = h*512+d) @ WoP + bo
    {
        dim3 grid(D_ / 128, M_ / 128, B_);
        hgemm_kernel<0, true><<<grid, 256, SHM_TOTAL>>>(at_hi, at_lo, WoP_hi,
            out, nullptr, nullptr, M_, D_, HD_, 1, 1, sAB, 0, sMD, 1.0f, bo, 0);
    }
}

// round 10
// speedup vs baseline: 4.3553x; 1.0987x over previous
#include <cuda_runtime.h>
#include <cuda_fp16.h>
#include <cstdint>

#define B_  8
#define N_  2048
#define M_  2048
#define D_  512
#define H_  8
#define BH_ (B_ * H_)
#define HD_ (H_ * D_)

// -------------------------------------------------------------------------
// Device scratch.  A-side operands keep fp16 hi/lo pairs (full precision);
// B-side operands are fp16 hi only (2-pass split scheme).
// -------------------------------------------------------------------------
__device__ __half g_kc_hi[(size_t)B_ * N_ * D_], g_kc_lo[(size_t)B_ * N_ * D_];
__device__ __half g_vc_hi[(size_t)B_ * N_ * D_], g_vc_lo[(size_t)B_ * N_ * D_];
__device__ __half g_qc_hi[(size_t)B_ * M_ * D_], g_qc_lo[(size_t)B_ * M_ * D_];
__device__ __half g_WkT_hi[(size_t)H_ * D_ * D_];
__device__ __half g_WvT_hi[(size_t)H_ * D_ * D_];
__device__ __half g_WqT_hi[(size_t)H_ * D_ * D_];
__device__ __half g_WoP_hi[(size_t)D_ * HD_];                  // [n=512][k=h*512+d]
__device__ __half g_kp_hi[(size_t)BH_ * N_ * D_];              // k' (B operand only)
__device__ __half g_qp_hi[(size_t)BH_ * M_ * D_], g_qp_lo[(size_t)BH_ * M_ * D_];
__device__ __half g_vT_hi[(size_t)BH_ * D_ * N_];              // v'^T (B operand only)
__device__ float  g_scores[(size_t)BH_ * M_ * N_];
__device__ __half g_P_hi[(size_t)BH_ * M_ * N_],  g_P_lo[(size_t)BH_ * M_ * N_];
__device__ __half g_at_hi[(size_t)BH_ * M_ * D_], g_at_lo[(size_t)BH_ * M_ * D_];

// -------------------------------------------------------------------------
// PTX helpers (family-baseline instructions only)
// -------------------------------------------------------------------------
__device__ __forceinline__ uint32_t smem_to_u32(const void* p) {
    uint32_t a;
    asm("{ .reg .u64 t; cvta.to.shared.u64 t, %1; cvt.u32.u64 %0, t; }" : "=r"(a) : "l"(p));
    return a;
}
__device__ __forceinline__ void cp16(uint32_t dst, const void* src) {
    asm volatile("cp.async.cg.shared.global [%0], [%1], 16;" :: "r"(dst), "l"(src));
}
#define CP_COMMIT() asm volatile("cp.async.commit_group;" ::: "memory")
#define CP_WAIT2()  asm volatile("cp.async.wait_group 2;" ::: "memory")

__device__ __forceinline__ void ldsm4(uint32_t* r, uint32_t addr) {
    asm volatile("ldmatrix.sync.aligned.m8n8.x4.shared.b16 {%0,%1,%2,%3}, [%4];"
                 : "=r"(r[0]), "=r"(r[1]), "=r"(r[2]), "=r"(r[3]) : "r"(addr));
}
__device__ __forceinline__ void mma16816(float* c, const uint32_t* a,
                                         uint32_t b0, uint32_t b1) {
    asm volatile("mma.sync.aligned.m16n8k16.row.col.f32.f16.f16.f32 "
                 "{%0,%1,%2,%3}, {%4,%5,%6,%7}, {%8,%9}, {%0,%1,%2,%3};"
                 : "+f"(c[0]), "+f"(c[1]), "+f"(c[2]), "+f"(c[3])
                 : "r"(a[0]), "r"(a[1]), "r"(a[2]), "r"(a[3]), "r"(b0), "r"(b1));
}
__device__ __forceinline__ void split(float v, __half& h, __half& l) {
    h = __float2half_rn(v);
    l = __float2half_rn(v - __half2float(h));
}

// -------------------------------------------------------------------------
// 2-pass fp16 tensor-core GEMM.  C[z] = alpha * A[z] @ B[z]^T (+ bias)
// A: [Md, Kd] fp16 hi/lo row-major.  B: [Nd, Kd] fp16 hi only, K-major.
// Passes: A_hi*B_hi + A_lo*B_hi.
// EPI: 0 = fp32 out; 1 = fp16 hi/lo pair out; 2 = fp16 hi transposed out;
//      3 = fp16 hi out (row-major).
// GA:  gather A from attention layout [h][m][d], k = h*512 + d.
// CTA tile 128(M) x 256(N), BK=64, 256 threads = 8 warps in 2(M) x 4(N)
// grid, warp tile 64x64.  3-stage cp.async pipeline; stage = A_hi(16K) +
// A_lo(16K) + B_hi(32K) = 64KB.
// -------------------------------------------------------------------------
#define STAGE_BYTES 65536
#define SHM_TOTAL   (3 * STAGE_BYTES)

template <int EPI, bool GA>
__global__ void __launch_bounds__(256, 1) hgemm_kernel(
    const __half* __restrict__ Ah, const __half* __restrict__ Al,
    const __half* __restrict__ Bh,
    float* __restrict__ Cf, __half* __restrict__ Ch, __half* __restrict__ Cl,
    int Md, int Nd, int Kd, int divA, int modB,
    long long strideA, long long strideB, long long strideC,
    float alpha, const float* __restrict__ bias, int biasStride)
{
    extern __shared__ char smem[];
    const uint32_t sm0 = smem_to_u32(smem);
    const int tid = threadIdx.x;
    const int wid = tid >> 5, lane = tid & 31;
    const int wm = wid >> 2, wn = wid & 3;      // 2(M) x 4(N) warp grid

    const int z = blockIdx.z;
    Ah += (long long)(z / divA) * strideA;
    Al += (long long)(z / divA) * strideA;
    Bh += (long long)(z % modB) * strideB;
    const long long coff = (long long)z * strideC;
    const float* bptr = bias ? (bias + (long long)(z % modB) * biasStride) : nullptr;
    const int m0 = blockIdx.y * 128;
    const int n0 = blockIdx.x * 256;

    const int nIter = Kd >> 6;

    // ---- cp.async stage issue: A_hi(1024 ch) + A_lo(1024) + B_hi(2048) ----
    auto issue = [&](int it, int st) {
        const uint32_t sb = sm0 + st * STAGE_BYTES;
        const int kb = it * 64;
        const long long ga_off = GA ? ((long long)(kb >> 9) * ((long long)M_ * D_) + (kb & 511))
                                    : 0;
        #pragma unroll
        for (int i = 0; i < 4; i++) {
            int ci = tid + i * 256;          // 0..1023
            int row = ci >> 3;               // 0..127
            int kc8 = ci & 7;
            uint32_t doff = row * 128 + ((kc8 * 16) ^ ((row & 7) << 4));
            const __half *sa, *sal;
            if (GA) {
                sa  = Ah + ga_off + (long long)(m0 + row) * D_ + kc8 * 8;
                sal = Al + ga_off + (long long)(m0 + row) * D_ + kc8 * 8;
            } else {
                sa  = Ah + (long long)(m0 + row) * Kd + kb + kc8 * 8;
                sal = Al + (long long)(m0 + row) * Kd + kb + kc8 * 8;
            }
            cp16(sb + doff,         sa);
            cp16(sb + 16384 + doff, sal);
        }
        #pragma unroll
        for (int i = 0; i < 8; i++) {
            int ci = tid + i * 256;          // 0..2047
            int row = ci >> 3;               // 0..255
            int kc8 = ci & 7;
            uint32_t doff = row * 128 + ((kc8 * 16) ^ ((row & 7) << 4));
            cp16(sb + 32768 + doff, Bh + (long long)(n0 + row) * Kd + kb + kc8 * 8);
        }
    };

    float acc[4][8][4];
    #pragma unroll
    for (int i = 0; i < 4; i++)
        #pragma unroll
        for (int j = 0; j < 8; j++)
            #pragma unroll
            for (int r = 0; r < 4; r++) acc[i][j][r] = 0.0f;

    issue(0, 0); CP_COMMIT();
    issue(1, 1); CP_COMMIT();
    issue(2, 2); CP_COMMIT();

    const int arow_l = wm * 64 + (lane & 15);
    const int akch   = (lane >> 4) << 4;
    const int brow_l = wn * 64 + ((lane >> 4) << 3) + (lane & 7);
    const int bkch   = ((lane >> 3) & 1) << 4;

    for (int it = 0; it < nIter; it++) {
        const int st = it - (it / 3) * 3;
        CP_WAIT2();
        __syncthreads();

        const uint32_t sb = sm0 + st * STAGE_BYTES;
        #pragma unroll
        for (int kc = 0; kc < 4; kc++) {
            uint32_t ah[4][4], al[4][4], bh[4][4];
            #pragma unroll
            for (int mf = 0; mf < 4; mf++) {
                int row = arow_l + mf * 16;
                uint32_t addr = sb + row * 128 + ((kc * 32 + akch) ^ ((row & 7) << 4));
                ldsm4(ah[mf], addr);
                ldsm4(al[mf], addr + 16384);
            }
            #pragma unroll
            for (int ng = 0; ng < 4; ng++) {
                int row = brow_l + ng * 16;
                uint32_t addr = sb + 32768 + row * 128 +
                                ((kc * 32 + bkch) ^ ((row & 7) << 4));
                ldsm4(bh[ng], addr);
            }
            #pragma unroll
            for (int mf = 0; mf < 4; mf++)
                #pragma unroll
                for (int nf = 0; nf < 8; nf++) {
                    const int ng = nf >> 1, j = nf & 1;
                    mma16816(acc[mf][nf], ah[mf], bh[ng][2 * j], bh[ng][2 * j + 1]);
                }
            #pragma unroll
            for (int mf = 0; mf < 4; mf++)
                #pragma unroll
                for (int nf = 0; nf < 8; nf++) {
                    const int ng = nf >> 1, j = nf & 1;
                    mma16816(acc[mf][nf], al[mf], bh[ng][2 * j], bh[ng][2 * j + 1]);
                }
        }
        __syncthreads();
        if (it + 3 < nIter) issue(it + 3, st);
        CP_COMMIT();
    }

    // ---- epilogue ----
    const int g   = lane >> 2;
    const int cp2 = (lane & 3) * 2;
    #pragma unroll
    for (int mf = 0; mf < 4; mf++) {
        #pragma unroll
        for (int nf = 0; nf < 8; nf++) {
            int row0 = m0 + wm * 64 + mf * 16 + g;
            int row1 = row0 + 8;
            int col  = n0 + wn * 64 + nf * 8 + cp2;
            float v00 = acc[mf][nf][0] * alpha;
            float v01 = acc[mf][nf][1] * alpha;
            float v10 = acc[mf][nf][2] * alpha;
            float v11 = acc[mf][nf][3] * alpha;
            if (bptr) {
                float b0 = bptr[col], b1 = bptr[col + 1];
                v00 += b0; v01 += b1; v10 += b0; v11 += b1;
            }
            if (EPI == 0) {
                *reinterpret_cast<float2*>(Cf + coff + (long long)row0 * Nd + col) =
                    make_float2(v00, v01);
                *reinterpret_cast<float2*>(Cf + coff + (long long)row1 * Nd + col) =
                    make_float2(v10, v11);
            } else if (EPI == 1) {
                __half h00, l00, h01, l01, h10, l10, h11, l11;
                split(v00, h00, l00); split(v01, h01, l01);
                split(v10, h10, l10); split(v11, h11, l11);
                __half2 hh0; hh0.x = h00; hh0.y = h01;
                __half2 ll0; ll0.x = l00; ll0.y = l01;
                __half2 hh1; hh1.x = h10; hh1.y = h11;
                __half2 ll1; ll1.x = l10; ll1.y = l11;
                *reinterpret_cast<__half2*>(Ch + coff + (long long)row0 * Nd + col) = hh0;
                *reinterpret_cast<__half2*>(Cl + coff + (long long)row0 * Nd + col) = ll0;
                *reinterpret_cast<__half2*>(Ch + coff + (long long)row1 * Nd + col) = hh1;
                *reinterpret_cast<__half2*>(Cl + coff + (long long)row1 * Nd + col) = ll1;
            } else if (EPI == 2) {
                Ch[coff + (long long)col * Md + row0]       = __float2half_rn(v00);
                Ch[coff + (long long)(col + 1) * Md + row0] = __float2half_rn(v01);
                Ch[coff + (long long)col * Md + row1]       = __float2half_rn(v10);
                Ch[coff + (long long)(col + 1) * Md + row1] = __float2half_rn(v11);
            } else {  // EPI == 3: hi only, row-major
                __half2 hh0; hh0.x = __float2half_rn(v00); hh0.y = __float2half_rn(v01);
                __half2 hh1; hh1.x = __float2half_rn(v10); hh1.y = __float2half_rn(v11);
                *reinterpret_cast<__half2*>(Ch + coff + (long long)row0 * Nd + col) = hh0;
                *reinterpret_cast<__half2*>(Ch + coff + (long long)row1 * Nd + col) = hh1;
            }
        }
    }
}

// -------------------------------------------------------------------------
// fp32 -> fp16 hi/lo split (elementwise)
// -------------------------------------------------------------------------
__global__ void __launch_bounds__(256) convsplit_kernel(
    const float* __restrict__ src, __half* __restrict__ hi,
    __half* __restrict__ lo, size_t n4)
{
    size_t i = (size_t)blockIdx.x * 256 + threadIdx.x;
    if (i >= n4) return;
    float4 v = reinterpret_cast<const float4*>(src)[i];
    __half h0, l0, h1, l1, h2, l2, h3, l3;
    split(v.x, h0, l0); split(v.y, h1, l1);
    split(v.z, h2, l2); split(v.w, h3, l3);
    __half2 ha; ha.x = h0; ha.y = h1;
    __half2 hb; hb.x = h2; hb.y = h3;
    __half2 la; la.x = l0; la.y = l1;
    __half2 lb; lb.x = l2; lb.y = l3;
    reinterpret_cast<__half2*>(hi)[2 * i]     = ha;
    reinterpret_cast<__half2*>(hi)[2 * i + 1] = hb;
    reinterpret_cast<__half2*>(lo)[2 * i]     = la;
    reinterpret_cast<__half2*>(lo)[2 * i + 1] = lb;
}

// -------------------------------------------------------------------------
// Batched transpose (hi only): dst[z][c][r] = fp16(src[z][r][c])
// -------------------------------------------------------------------------
__global__ void __launch_bounds__(256) transpose_h_kernel(
    const float* __restrict__ src, __half* __restrict__ hi, int R, int C)
{
    __shared__ float t[32][33];
    const size_t zoff = (size_t)blockIdx.z * R * C;
    int tx = threadIdx.x, ty = threadIdx.y;
    int x = blockIdx.x * 32 + tx;
    int y = blockIdx.y * 32 + ty;
    #pragma unroll
    for (int j = 0; j < 32; j += 8)
        t[ty + j][tx] = src[zoff + (size_t)(y + j) * C + x];
    __syncthreads();
    int x2 = blockIdx.y * 32 + tx;
    int y2 = blockIdx.x * 32 + ty;
    #pragma unroll
    for (int j = 0; j < 32; j += 8)
        hi[zoff + (size_t)(y2 + j) * R + x2] = __float2half_rn(t[tx][ty + j]);
}

// -------------------------------------------------------------------------
// Wo permute+transpose (hi only): out[n][k = h*512+d] = fp16(Wo[d*8+h][n])
// -------------------------------------------------------------------------
__global__ void __launch_bounds__(256) wo_permute_h_kernel(
    const float* __restrict__ Wo, __half* __restrict__ hi)
{
    __shared__ float t[32][33];
    int tx = threadIdx.x, ty = threadIdx.y;       // 32 x 8
    int kb = blockIdx.x * 32;
    int nb = blockIdx.y * 32;
    int h  = kb >> 9;
    int d0 = kb & 511;
    #pragma unroll
    for (int j = 0; j < 32; j += 8) {
        int d = d0 + ty + j;
        t[ty + j][tx] = Wo[(size_t)(d * 8 + h) * D_ + nb + tx];
    }
    __syncthreads();
    #pragma unroll
    for (int j = 0; j < 32; j += 8) {
        int n = nb + ty + j;
        hi[(size_t)n * HD_ + kb + tx] = __float2half_rn(t[tx][ty + j]);
    }
}

// -------------------------------------------------------------------------
// Row softmax over N_=2048, emits fp16 hi/lo probability arrays.
// -------------------------------------------------------------------------
__global__ void __launch_bounds__(256) softmax_kernel(
    const float* __restrict__ S, __half* __restrict__ Ph, __half* __restrict__ Pl)
{
    const long long roff = (long long)blockIdx.x * N_;
    const float* p = S + roff;
    const int tid = threadIdx.x;

    float4 v0 = *reinterpret_cast<const float4*>(p + tid * 8);
    float4 v1 = *reinterpret_cast<const float4*>(p + tid * 8 + 4);

    float m = fmaxf(fmaxf(fmaxf(v0.x, v0.y), fmaxf(v0.z, v0.w)),
                    fmaxf(fmaxf(v1.x, v1.y), fmaxf(v1.z, v1.w)));
    #pragma unroll
    for (int o = 16; o > 0; o >>= 1)
        m = fmaxf(m, __shfl_xor_sync(0xffffffffu, m, o));

    __shared__ float smax[8];
    __shared__ float ssum[8];
    if ((tid & 31) == 0) smax[tid >> 5] = m;
    __syncthreads();
    m = smax[0];
    #pragma unroll
    for (int i = 1; i < 8; i++) m = fmaxf(m, smax[i]);

    v0.x = __expf(v0.x - m); v0.y = __expf(v0.y - m);
    v0.z = __expf(v0.z - m); v0.w = __expf(v0.w - m);
    v1.x = __expf(v1.x - m); v1.y = __expf(v1.y - m);
    v1.z = __expf(v1.z - m); v1.w = __expf(v1.w - m);

    float s = v0.x + v0.y + v0.z + v0.w + v1.x + v1.y + v1.z + v1.w;
    #pragma unroll
    for (int o = 16; o > 0; o >>= 1)
        s += __shfl_xor_sync(0xffffffffu, s, o);
    if ((tid & 31) == 0) ssum[tid >> 5] = s;
    __syncthreads();
    s = 0.0f;
    #pragma unroll
    for (int i = 0; i < 8; i++) s += ssum[i];

    const float inv = 1.0f / s;
    float pv[8] = { v0.x * inv, v0.y * inv, v0.z * inv, v0.w * inv,
                    v1.x * inv, v1.y * inv, v1.z * inv, v1.w * inv };
    __half2 hh[4], ll[4];
    #pragma unroll
    for (int i = 0; i < 4; i++) {
        __half h0, l0, h1, l1;
        split(pv[2 * i], h0, l0);
        split(pv[2 * i + 1], h1, l1);
        hh[i].x = h0; hh[i].y = h1;
        ll[i].x = l0; ll[i].y = l1;
    }
    *reinterpret_cast<uint4*>(Ph + roff + tid * 8) = *reinterpret_cast<uint4*>(hh);
    *reinterpret_cast<uint4*>(Pl + roff + tid * 8) = *reinterpret_cast<uint4*>(ll);
}

// -------------------------------------------------------------------------
// Launch
// -------------------------------------------------------------------------
extern "C" void kernel_launch(void* const* d_in, const int* in_sizes, int n_in,
                              void* d_out, int out_size)
{
    (void)in_sizes; (void)n_in; (void)out_size;
    const float* k  = (const float*)d_in[0];
    const float* v  = (const float*)d_in[1];
    const float* q  = (const float*)d_in[2];
    const float* Wk = (const float*)d_in[3];
    const float* bk = (const float*)d_in[4];
    const float* Wv = (const float*)d_in[5];
    const float* bv = (const float*)d_in[6];
    const float* Wq = (const float*)d_in[7];
    const float* bq = (const float*)d_in[8];
    const float* Wo = (const float*)d_in[9];
    const float* bo = (const float*)d_in[10];
    float* out = (float*)d_out;

    __half *kc_hi, *kc_lo, *vc_hi, *vc_lo, *qc_hi, *qc_lo;
    __half *WkT_hi, *WvT_hi, *WqT_hi, *WoP_hi;
    __half *kp_hi, *qp_hi, *qp_lo, *vT_hi;
    __half *P_hi, *P_lo, *at_hi, *at_lo;
    float *sc;
    cudaGetSymbolAddress((void**)&kc_hi, g_kc_hi);  cudaGetSymbolAddress((void**)&kc_lo, g_kc_lo);
    cudaGetSymbolAddress((void**)&vc_hi, g_vc_hi);  cudaGetSymbolAddress((void**)&vc_lo, g_vc_lo);
    cudaGetSymbolAddress((void**)&qc_hi, g_qc_hi);  cudaGetSymbolAddress((void**)&qc_lo, g_qc_lo);
    cudaGetSymbolAddress((void**)&WkT_hi, g_WkT_hi);
    cudaGetSymbolAddress((void**)&WvT_hi, g_WvT_hi);
    cudaGetSymbolAddress((void**)&WqT_hi, g_WqT_hi);
    cudaGetSymbolAddress((void**)&WoP_hi, g_WoP_hi);
    cudaGetSymbolAddress((void**)&kp_hi, g_kp_hi);
    cudaGetSymbolAddress((void**)&qp_hi, g_qp_hi);  cudaGetSymbolAddress((void**)&qp_lo, g_qp_lo);
    cudaGetSymbolAddress((void**)&vT_hi, g_vT_hi);
    cudaGetSymbolAddress((void**)&P_hi, g_P_hi);    cudaGetSymbolAddress((void**)&P_lo, g_P_lo);
    cudaGetSymbolAddress((void**)&at_hi, g_at_hi);  cudaGetSymbolAddress((void**)&at_lo, g_at_lo);
    cudaGetSymbolAddress((void**)&sc, g_scores);

    const long long sND = (long long)N_ * D_;
    const long long sDD = (long long)D_ * D_;
    const long long sMN = (long long)M_ * N_;
    const long long sMD = (long long)M_ * D_;
    const long long sAB = (long long)H_ * M_ * D_;   // attn batch stride

    cudaFuncSetAttribute(hgemm_kernel<0, false>, cudaFuncAttributeMaxDynamicSharedMemorySize, SHM_TOTAL);
    cudaFuncSetAttribute(hgemm_kernel<1, false>, cudaFuncAttributeMaxDynamicSharedMemorySize, SHM_TOTAL);
    cudaFuncSetAttribute(hgemm_kernel<2, false>, cudaFuncAttributeMaxDynamicSharedMemorySize, SHM_TOTAL);
    cudaFuncSetAttribute(hgemm_kernel<3, false>, cudaFuncAttributeMaxDynamicSharedMemorySize, SHM_TOTAL);
    cudaFuncSetAttribute(hgemm_kernel<0, true>,  cudaFuncAttributeMaxDynamicSharedMemorySize, SHM_TOTAL);

    // 0) split inputs, convert weights (hi only)
    {
        size_t n4 = (size_t)B_ * N_ * D_ / 4;
        int gb = (int)((n4 + 255) / 256);
        convsplit_kernel<<<gb, 256>>>(k, kc_hi, kc_lo, n4);
        convsplit_kernel<<<gb, 256>>>(v, vc_hi, vc_lo, n4);
        convsplit_kernel<<<gb, 256>>>(q, qc_hi, qc_lo, n4);
        dim3 tb(32, 8);
        transpose_h_kernel<<<dim3(D_ / 32, D_ / 32, H_), tb>>>(Wk, WkT_hi, D_, D_);
        transpose_h_kernel<<<dim3(D_ / 32, D_ / 32, H_), tb>>>(Wv, WvT_hi, D_, D_);
        transpose_h_kernel<<<dim3(D_ / 32, D_ / 32, H_), tb>>>(Wq, WqT_hi, D_, D_);
        wo_permute_h_kernel<<<dim3(HD_ / 32, D_ / 32), tb>>>(Wo, WoP_hi);
    }

    // 1) projections: k' hi-only, q' pair, v' hi-only transposed
    {
        dim3 grid(D_ / 256, N_ / 128, BH_);
        hgemm_kernel<3, false><<<grid, 256, SHM_TOTAL>>>(kc_hi, kc_lo, WkT_hi,
            nullptr, kp_hi, nullptr, N_, D_, D_, H_, H_, sND, sDD, sND, 1.0f, bk, D_);
        hgemm_kernel<1, false><<<grid, 256, SHM_TOTAL>>>(qc_hi, qc_lo, WqT_hi,
            nullptr, qp_hi, qp_lo, M_, D_, D_, H_, H_, sND, sDD, sND, 1.0f, bq, D_);
        hgemm_kernel<2, false><<<grid, 256, SHM_TOTAL>>>(vc_hi, vc_lo, WvT_hi,
            nullptr, vT_hi, nullptr, N_, D_, D_, H_, H_, sND, sDD, sND, 1.0f, bv, D_);
    }

    // 2) scores = (q' @ k'^T) / sqrt(D)
    {
        dim3 grid(N_ / 256, M_ / 128, BH_);
        const float scale = 0.044194173824159216f;
        hgemm_kernel<0, false><<<grid, 256, SHM_TOTAL>>>(qp_hi, qp_lo, kp_hi,
            sc, nullptr, nullptr, M_, N_, D_, 1, BH_, sMD, sND, sMN, scale, nullptr, 0);
    }

    // 3) softmax -> P hi/lo
    softmax_kernel<<<BH_ * M_, 256>>>(sc, P_hi, P_lo);

    // 4) attn = P @ v'  -> fp16 hi/lo, layout [z][m][d]
    {
        dim3 grid(D_ / 256, M_ / 128, BH_);
        hgemm_kernel<1, false><<<grid, 256, SHM_TOTAL>>>(P_hi, P_lo, vT_hi,
            nullptr, at_hi, at_lo, M_, D_, N_, 1, BH_, sMN, sND, sMD, 1.0f, nullptr, 0);
    }

    // 5) out = attn(gathered, k = h*512+d) @ WoP + bo
    {
        dim3 grid(D_ / 256, M_ / 128, B_);
        hgemm_kernel<0, true><<<grid, 256, SHM_TOTAL>>>(at_hi, at_lo, WoP_hi,
            out, nullptr, nullptr, M_, D_, HD_, 1, 1, sAB, 0, sMD, 1.0f, bo, 0);
    }
}

// round 11
// speedup vs baseline: 5.8966x; 1.3539x over previous
#include <cuda_runtime.h>
#include <cuda_fp16.h>
#include <cstdint>

#define B_  8
#define N_  2048
#define M_  2048
#define D_  512
#define H_  8
#define BH_ (B_ * H_)
#define HD_ (H_ * D_)

// -------------------------------------------------------------------------
// Device scratch.
// 2-pass GEMMs (projections, outproj): A-side fp16 hi/lo.
// 1-pass GEMMs (scores, PV): A-side fp16 hi only.
// All B-side operands fp16 hi only.
// -------------------------------------------------------------------------
__device__ __half g_kc_hi[(size_t)B_ * N_ * D_], g_kc_lo[(size_t)B_ * N_ * D_];
__device__ __half g_vc_hi[(size_t)B_ * N_ * D_], g_vc_lo[(size_t)B_ * N_ * D_];
__device__ __half g_qc_hi[(size_t)B_ * M_ * D_], g_qc_lo[(size_t)B_ * M_ * D_];
__device__ __half g_WkT_hi[(size_t)H_ * D_ * D_];
__device__ __half g_WvT_hi[(size_t)H_ * D_ * D_];
__device__ __half g_WqT_hi[(size_t)H_ * D_ * D_];
__device__ __half g_WoP_hi[(size_t)D_ * HD_];                  // [n=512][k=h*512+d]
__device__ __half g_kp_hi[(size_t)BH_ * N_ * D_];              // k'
__device__ __half g_qp_hi[(size_t)BH_ * M_ * D_];              // q' (hi only now)
__device__ __half g_vT_hi[(size_t)BH_ * D_ * N_];              // v'^T
__device__ float  g_scores[(size_t)BH_ * M_ * N_];
__device__ __half g_P_hi[(size_t)BH_ * M_ * N_];               // P (hi only now)
__device__ __half g_at_hi[(size_t)BH_ * M_ * D_], g_at_lo[(size_t)BH_ * M_ * D_];

// -------------------------------------------------------------------------
// PTX helpers (family-baseline instructions only)
// -------------------------------------------------------------------------
__device__ __forceinline__ uint32_t smem_to_u32(const void* p) {
    uint32_t a;
    asm("{ .reg .u64 t; cvta.to.shared.u64 t, %1; cvt.u32.u64 %0, t; }" : "=r"(a) : "l"(p));
    return a;
}
__device__ __forceinline__ void cp16(uint32_t dst, const void* src) {
    asm volatile("cp.async.cg.shared.global [%0], [%1], 16;" :: "r"(dst), "l"(src));
}
#define CP_COMMIT() asm volatile("cp.async.commit_group;" ::: "memory")
#define CP_WAIT2()  asm volatile("cp.async.wait_group 2;" ::: "memory")

__device__ __forceinline__ void ldsm4(uint32_t* r, uint32_t addr) {
    asm volatile("ldmatrix.sync.aligned.m8n8.x4.shared.b16 {%0,%1,%2,%3}, [%4];"
                 : "=r"(r[0]), "=r"(r[1]), "=r"(r[2]), "=r"(r[3]) : "r"(addr));
}
__device__ __forceinline__ void mma16816(float* c, const uint32_t* a,
                                         uint32_t b0, uint32_t b1) {
    asm volatile("mma.sync.aligned.m16n8k16.row.col.f32.f16.f16.f32 "
                 "{%0,%1,%2,%3}, {%4,%5,%6,%7}, {%8,%9}, {%0,%1,%2,%3};"
                 : "+f"(c[0]), "+f"(c[1]), "+f"(c[2]), "+f"(c[3])
                 : "r"(a[0]), "r"(a[1]), "r"(a[2]), "r"(a[3]), "r"(b0), "r"(b1));
}
__device__ __forceinline__ void split(float v, __half& h, __half& l) {
    h = __float2half_rn(v);
    l = __float2half_rn(v - __half2float(h));
}

// -------------------------------------------------------------------------
// fp16 tensor-core GEMM.  C[z] = alpha * A[z] @ B[z]^T (+ bias)
// PASSES=2: A fp16 hi/lo, passes A_hi*B + A_lo*B.  Stage: Ah 16K | Al 16K | B 32K.
// PASSES=1: A fp16 hi only.                         Stage: Ah 16K | B 32K.
// EPI: 0 = fp32 out; 1 = fp16 hi/lo pair out; 2 = fp16 hi transposed out;
//      3 = fp16 hi out (row-major).
// GA:  gather A from attention layout [h][m][d], k = h*512 + d.
// CTA tile 128(M) x 256(N), BK=64, 256 threads (2x4 warps), warp tile 64x64,
// 3-stage cp.async pipeline.
// -------------------------------------------------------------------------
template <int EPI, bool GA, int PASSES>
__global__ void __launch_bounds__(256, 1) hgemm_kernel(
    const __half* __restrict__ Ah, const __half* __restrict__ Al,
    const __half* __restrict__ Bh,
    float* __restrict__ Cf, __half* __restrict__ Ch, __half* __restrict__ Cl,
    int Md, int Nd, int Kd, int divA, int modB,
    long long strideA, long long strideB, long long strideC,
    float alpha, const float* __restrict__ bias, int biasStride)
{
    constexpr uint32_t BOFF = (PASSES == 2) ? 32768u : 16384u;
    constexpr uint32_t STAGE = BOFF + 32768u;        // 64KB or 48KB

    extern __shared__ char smem[];
    const uint32_t sm0 = smem_to_u32(smem);
    const int tid = threadIdx.x;
    const int wid = tid >> 5, lane = tid & 31;
    const int wm = wid >> 2, wn = wid & 3;           // 2(M) x 4(N) warp grid

    const int z = blockIdx.z;
    Ah += (long long)(z / divA) * strideA;
    if (PASSES == 2) Al += (long long)(z / divA) * strideA;
    Bh += (long long)(z % modB) * strideB;
    const long long coff = (long long)z * strideC;
    const float* bptr = bias ? (bias + (long long)(z % modB) * biasStride) : nullptr;
    const int m0 = blockIdx.y * 128;
    const int n0 = blockIdx.x * 256;

    const int nIter = Kd >> 6;

    auto issue = [&](int it, int st) {
        const uint32_t sb = sm0 + st * STAGE;
        const int kb = it * 64;
        const long long ga_off = GA ? ((long long)(kb >> 9) * ((long long)M_ * D_) + (kb & 511))
                                    : 0;
        #pragma unroll
        for (int i = 0; i < 4; i++) {
            int ci = tid + i * 256;          // 0..1023
            int row = ci >> 3;               // 0..127
            int kc8 = ci & 7;
            uint32_t doff = row * 128 + ((kc8 * 16) ^ ((row & 7) << 4));
            const __half *sa, *sal;
            if (GA) {
                sa  = Ah + ga_off + (long long)(m0 + row) * D_ + kc8 * 8;
                sal = (PASSES == 2) ? Al + ga_off + (long long)(m0 + row) * D_ + kc8 * 8 : nullptr;
            } else {
                sa  = Ah + (long long)(m0 + row) * Kd + kb + kc8 * 8;
                sal = (PASSES == 2) ? Al + (long long)(m0 + row) * Kd + kb + kc8 * 8 : nullptr;
            }
            cp16(sb + doff, sa);
            if (PASSES == 2) cp16(sb + 16384 + doff, sal);
        }
        #pragma unroll
        for (int i = 0; i < 8; i++) {
            int ci = tid + i * 256;          // 0..2047
            int row = ci >> 3;               // 0..255
            int kc8 = ci & 7;
            uint32_t doff = row * 128 + ((kc8 * 16) ^ ((row & 7) << 4));
            cp16(sb + BOFF + doff, Bh + (long long)(n0 + row) * Kd + kb + kc8 * 8);
        }
    };

    float acc[4][8][4];
    #pragma unroll
    for (int i = 0; i < 4; i++)
        #pragma unroll
        for (int j = 0; j < 8; j++)
            #pragma unroll
            for (int r = 0; r < 4; r++) acc[i][j][r] = 0.0f;

    issue(0, 0); CP_COMMIT();
    issue(1, 1); CP_COMMIT();
    issue(2, 2); CP_COMMIT();

    const int arow_l = wm * 64 + (lane & 15);
    const int akch   = (lane >> 4) << 4;
    const int brow_l = wn * 64 + ((lane >> 4) << 3) + (lane & 7);
    const int bkch   = ((lane >> 3) & 1) << 4;

    for (int it = 0; it < nIter; it++) {
        const int st = it - (it / 3) * 3;
        CP_WAIT2();
        __syncthreads();

        const uint32_t sb = sm0 + st * STAGE;
        #pragma unroll
        for (int kc = 0; kc < 4; kc++) {
            uint32_t ah[4][4], al[4][4], bh[4][4];
            #pragma unroll
            for (int mf = 0; mf < 4; mf++) {
                int row = arow_l + mf * 16;
                uint32_t addr = sb + row * 128 + ((kc * 32 + akch) ^ ((row & 7) << 4));
                ldsm4(ah[mf], addr);
                if (PASSES == 2) ldsm4(al[mf], addr + 16384);
            }
            #pragma unroll
            for (int ng = 0; ng < 4; ng++) {
                int row = brow_l + ng * 16;
                uint32_t addr = sb + BOFF + row * 128 +
                                ((kc * 32 + bkch) ^ ((row & 7) << 4));
                ldsm4(bh[ng], addr);
            }
            #pragma unroll
            for (int mf = 0; mf < 4; mf++)
                #pragma unroll
                for (int nf = 0; nf < 8; nf++) {
                    const int ng = nf >> 1, j = nf & 1;
                    mma16816(acc[mf][nf], ah[mf], bh[ng][2 * j], bh[ng][2 * j + 1]);
                }
            if (PASSES == 2) {
                #pragma unroll
                for (int mf = 0; mf < 4; mf++)
                    #pragma unroll
                    for (int nf = 0; nf < 8; nf++) {
                        const int ng = nf >> 1, j = nf & 1;
                        mma16816(acc[mf][nf], al[mf], bh[ng][2 * j], bh[ng][2 * j + 1]);
                    }
            }
        }
        __syncthreads();
        if (it + 3 < nIter) issue(it + 3, st);
        CP_COMMIT();
    }

    // ---- epilogue ----
    const int g   = lane >> 2;
    const int cp2 = (lane & 3) * 2;
    #pragma unroll
    for (int mf = 0; mf < 4; mf++) {
        #pragma unroll
        for (int nf = 0; nf < 8; nf++) {
            int row0 = m0 + wm * 64 + mf * 16 + g;
            int row1 = row0 + 8;
            int col  = n0 + wn * 64 + nf * 8 + cp2;
            float v00 = acc[mf][nf][0] * alpha;
            float v01 = acc[mf][nf][1] * alpha;
            float v10 = acc[mf][nf][2] * alpha;
            float v11 = acc[mf][nf][3] * alpha;
            if (bptr) {
                float b0 = bptr[col], b1 = bptr[col + 1];
                v00 += b0; v01 += b1; v10 += b0; v11 += b1;
            }
            if (EPI == 0) {
                *reinterpret_cast<float2*>(Cf + coff + (long long)row0 * Nd + col) =
                    make_float2(v00, v01);
                *reinterpret_cast<float2*>(Cf + coff + (long long)row1 * Nd + col) =
                    make_float2(v10, v11);
            } else if (EPI == 1) {
                __half h00, l00, h01, l01, h10, l10, h11, l11;
                split(v00, h00, l00); split(v01, h01, l01);
                split(v10, h10, l10); split(v11, h11, l11);
                __half2 hh0; hh0.x = h00; hh0.y = h01;
                __half2 ll0; ll0.x = l00; ll0.y = l01;
                __half2 hh1; hh1.x = h10; hh1.y = h11;
                __half2 ll1; ll1.x = l10; ll1.y = l11;
                *reinterpret_cast<__half2*>(Ch + coff + (long long)row0 * Nd + col) = hh0;
                *reinterpret_cast<__half2*>(Cl + coff + (long long)row0 * Nd + col) = ll0;
                *reinterpret_cast<__half2*>(Ch + coff + (long long)row1 * Nd + col) = hh1;
                *reinterpret_cast<__half2*>(Cl + coff + (long long)row1 * Nd + col) = ll1;
            } else if (EPI == 2) {
                Ch[coff + (long long)col * Md + row0]       = __float2half_rn(v00);
                Ch[coff + (long long)(col + 1) * Md + row0] = __float2half_rn(v01);
                Ch[coff + (long long)col * Md + row1]       = __float2half_rn(v10);
                Ch[coff + (long long)(col + 1) * Md + row1] = __float2half_rn(v11);
            } else {  // EPI == 3: hi only, row-major
                __half2 hh0; hh0.x = __float2half_rn(v00); hh0.y = __float2half_rn(v01);
                __half2 hh1; hh1.x = __float2half_rn(v10); hh1.y = __float2half_rn(v11);
                *reinterpret_cast<__half2*>(Ch + coff + (long long)row0 * Nd + col) = hh0;
                *reinterpret_cast<__half2*>(Ch + coff + (long long)row1 * Nd + col) = hh1;
            }
        }
    }
}

#define SHM_2P (3 * 65536)
#define SHM_1P (3 * 49152)

// -------------------------------------------------------------------------
// fp32 -> fp16 hi/lo split (elementwise)
// -------------------------------------------------------------------------
__global__ void __launch_bounds__(256) convsplit_kernel(
    const float* __restrict__ src, __half* __restrict__ hi,
    __half* __restrict__ lo, size_t n4)
{
    size_t i = (size_t)blockIdx.x * 256 + threadIdx.x;
    if (i >= n4) return;
    float4 v = reinterpret_cast<const float4*>(src)[i];
    __half h0, l0, h1, l1, h2, l2, h3, l3;
    split(v.x, h0, l0); split(v.y, h1, l1);
    split(v.z, h2, l2); split(v.w, h3, l3);
    __half2 ha; ha.x = h0; ha.y = h1;
    __half2 hb; hb.x = h2; hb.y = h3;
    __half2 la; la.x = l0; la.y = l1;
    __half2 lb; lb.x = l2; lb.y = l3;
    reinterpret_cast<__half2*>(hi)[2 * i]     = ha;
    reinterpret_cast<__half2*>(hi)[2 * i + 1] = hb;
    reinterpret_cast<__half2*>(lo)[2 * i]     = la;
    reinterpret_cast<__half2*>(lo)[2 * i + 1] = lb;
}

// -------------------------------------------------------------------------
// Batched transpose (hi only): dst[z][c][r] = fp16(src[z][r][c])
// -------------------------------------------------------------------------
__global__ void __launch_bounds__(256) transpose_h_kernel(
    const float* __restrict__ src, __half* __restrict__ hi, int R, int C)
{
    __shared__ float t[32][33];
    const size_t zoff = (size_t)blockIdx.z * R * C;
    int tx = threadIdx.x, ty = threadIdx.y;
    int x = blockIdx.x * 32 + tx;
    int y = blockIdx.y * 32 + ty;
    #pragma unroll
    for (int j = 0; j < 32; j += 8)
        t[ty + j][tx] = src[zoff + (size_t)(y + j) * C + x];
    __syncthreads();
    int x2 = blockIdx.y * 32 + tx;
    int y2 = blockIdx.x * 32 + ty;
    #pragma unroll
    for (int j = 0; j < 32; j += 8)
        hi[zoff + (size_t)(y2 + j) * R + x2] = __float2half_rn(t[tx][ty + j]);
}

// -------------------------------------------------------------------------
// Wo permute+transpose (hi only): out[n][k = h*512+d] = fp16(Wo[d*8+h][n])
// -------------------------------------------------------------------------
__global__ void __launch_bounds__(256) wo_permute_h_kernel(
    const float* __restrict__ Wo, __half* __restrict__ hi)
{
    __shared__ float t[32][33];
    int tx = threadIdx.x, ty = threadIdx.y;       // 32 x 8
    int kb = blockIdx.x * 32;
    int nb = blockIdx.y * 32;
    int h  = kb >> 9;
    int d0 = kb & 511;
    #pragma unroll
    for (int j = 0; j < 32; j += 8) {
        int d = d0 + ty + j;
        t[ty + j][tx] = Wo[(size_t)(d * 8 + h) * D_ + nb + tx];
    }
    __syncthreads();
    #pragma unroll
    for (int j = 0; j < 32; j += 8) {
        int n = nb + ty + j;
        hi[(size_t)n * HD_ + kb + tx] = __float2half_rn(t[tx][ty + j]);
    }
}

// -------------------------------------------------------------------------
// Row softmax over N_=2048, emits fp16 hi probability array.
// -------------------------------------------------------------------------
__global__ void __launch_bounds__(256) softmax_kernel(
    const float* __restrict__ S, __half* __restrict__ Ph)
{
    const long long roff = (long long)blockIdx.x * N_;
    const float* p = S + roff;
    const int tid = threadIdx.x;

    float4 v0 = *reinterpret_cast<const float4*>(p + tid * 8);
    float4 v1 = *reinterpret_cast<const float4*>(p + tid * 8 + 4);

    float m = fmaxf(fmaxf(fmaxf(v0.x, v0.y), fmaxf(v0.z, v0.w)),
                    fmaxf(fmaxf(v1.x, v1.y), fmaxf(v1.z, v1.w)));
    #pragma unroll
    for (int o = 16; o > 0; o >>= 1)
        m = fmaxf(m, __shfl_xor_sync(0xffffffffu, m, o));

    __shared__ float smax[8];
    __shared__ float ssum[8];
    if ((tid & 31) == 0) smax[tid >> 5] = m;
    __syncthreads();
    m = smax[0];
    #pragma unroll
    for (int i = 1; i < 8; i++) m = fmaxf(m, smax[i]);

    v0.x = __expf(v0.x - m); v0.y = __expf(v0.y - m);
    v0.z = __expf(v0.z - m); v0.w = __expf(v0.w - m);
    v1.x = __expf(v1.x - m); v1.y = __expf(v1.y - m);
    v1.z = __expf(v1.z - m); v1.w = __expf(v1.w - m);

    float s = v0.x + v0.y + v0.z + v0.w + v1.x + v1.y + v1.z + v1.w;
    #pragma unroll
    for (int o = 16; o > 0; o >>= 1)
        s += __shfl_xor_sync(0xffffffffu, s, o);
    if ((tid & 31) == 0) ssum[tid >> 5] = s;
    __syncthreads();
    s = 0.0f;
    #pragma unroll
    for (int i = 0; i < 8; i++) s += ssum[i];

    const float inv = 1.0f / s;
    __half2 hh[4];
    hh[0].x = __float2half_rn(v0.x * inv); hh[0].y = __float2half_rn(v0.y * inv);
    hh[1].x = __float2half_rn(v0.z * inv); hh[1].y = __float2half_rn(v0.w * inv);
    hh[2].x = __float2half_rn(v1.x * inv); hh[2].y = __float2half_rn(v1.y * inv);
    hh[3].x = __float2half_rn(v1.z * inv); hh[3].y = __float2half_rn(v1.w * inv);
    *reinterpret_cast<uint4*>(Ph + roff + tid * 8) = *reinterpret_cast<uint4*>(hh);
}

// -------------------------------------------------------------------------
// Launch
// -------------------------------------------------------------------------
extern "C" void kernel_launch(void* const* d_in, const int* in_sizes, int n_in,
                              void* d_out, int out_size)
{
    (void)in_sizes; (void)n_in; (void)out_size;
    const float* k  = (const float*)d_in[0];
    const float* v  = (const float*)d_in[1];
    const float* q  = (const float*)d_in[2];
    const float* Wk = (const float*)d_in[3];
    const float* bk = (const float*)d_in[4];
    const float* Wv = (const float*)d_in[5];
    const float* bv = (const float*)d_in[6];
    const float* Wq = (const float*)d_in[7];
    const float* bq = (const float*)d_in[8];
    const float* Wo = (const float*)d_in[9];
    const float* bo = (const float*)d_in[10];
    float* out = (float*)d_out;

    __half *kc_hi, *kc_lo, *vc_hi, *vc_lo, *qc_hi, *qc_lo;
    __half *WkT_hi, *WvT_hi, *WqT_hi, *WoP_hi;
    __half *kp_hi, *qp_hi, *vT_hi;
    __half *P_hi, *at_hi, *at_lo;
    float *sc;
    cudaGetSymbolAddress((void**)&kc_hi, g_kc_hi);  cudaGetSymbolAddress((void**)&kc_lo, g_kc_lo);
    cudaGetSymbolAddress((void**)&vc_hi, g_vc_hi);  cudaGetSymbolAddress((void**)&vc_lo, g_vc_lo);
    cudaGetSymbolAddress((void**)&qc_hi, g_qc_hi);  cudaGetSymbolAddress((void**)&qc_lo, g_qc_lo);
    cudaGetSymbolAddress((void**)&WkT_hi, g_WkT_hi);
    cudaGetSymbolAddress((void**)&WvT_hi, g_WvT_hi);
    cudaGetSymbolAddress((void**)&WqT_hi, g_WqT_hi);
    cudaGetSymbolAddress((void**)&WoP_hi, g_WoP_hi);
    cudaGetSymbolAddress((void**)&kp_hi, g_kp_hi);
    cudaGetSymbolAddress((void**)&qp_hi, g_qp_hi);
    cudaGetSymbolAddress((void**)&vT_hi, g_vT_hi);
    cudaGetSymbolAddress((void**)&P_hi, g_P_hi);
    cudaGetSymbolAddress((void**)&at_hi, g_at_hi);  cudaGetSymbolAddress((void**)&at_lo, g_at_lo);
    cudaGetSymbolAddress((void**)&sc, g_scores);

    const long long sND = (long long)N_ * D_;
    const long long sDD = (long long)D_ * D_;
    const long long sMN = (long long)M_ * N_;
    const long long sMD = (long long)M_ * D_;
    const long long sAB = (long long)H_ * M_ * D_;   // attn batch stride

    cudaFuncSetAttribute(hgemm_kernel<1, false, 2>, cudaFuncAttributeMaxDynamicSharedMemorySize, SHM_2P);
    cudaFuncSetAttribute(hgemm_kernel<2, false, 2>, cudaFuncAttributeMaxDynamicSharedMemorySize, SHM_2P);
    cudaFuncSetAttribute(hgemm_kernel<3, false, 2>, cudaFuncAttributeMaxDynamicSharedMemorySize, SHM_2P);
    cudaFuncSetAttribute(hgemm_kernel<0, true, 2>,  cudaFuncAttributeMaxDynamicSharedMemorySize, SHM_2P);
    cudaFuncSetAttribute(hgemm_kernel<0, false, 1>, cudaFuncAttributeMaxDynamicSharedMemorySize, SHM_1P);
    cudaFuncSetAttribute(hgemm_kernel<1, false, 1>, cudaFuncAttributeMaxDynamicSharedMemorySize, SHM_1P);

    // 0) split inputs, convert weights (hi only)
    {
        size_t n4 = (size_t)B_ * N_ * D_ / 4;
        int gb = (int)((n4 + 255) / 256);
        convsplit_kernel<<<gb, 256>>>(k, kc_hi, kc_lo, n4);
        convsplit_kernel<<<gb, 256>>>(v, vc_hi, vc_lo, n4);
        convsplit_kernel<<<gb, 256>>>(q, qc_hi, qc_lo, n4);
        dim3 tb(32, 8);
        transpose_h_kernel<<<dim3(D_ / 32, D_ / 32, H_), tb>>>(Wk, WkT_hi, D_, D_);
        transpose_h_kernel<<<dim3(D_ / 32, D_ / 32, H_), tb>>>(Wv, WvT_hi, D_, D_);
        transpose_h_kernel<<<dim3(D_ / 32, D_ / 32, H_), tb>>>(Wq, WqT_hi, D_, D_);
        wo_permute_h_kernel<<<dim3(HD_ / 32, D_ / 32), tb>>>(Wo, WoP_hi);
    }

    // 1) projections (2-pass): k' hi-only, q' hi-only, v' hi-only transposed
    {
        dim3 grid(D_ / 256, N_ / 128, BH_);
        hgemm_kernel<3, false, 2><<<grid, 256, SHM_2P>>>(kc_hi, kc_lo, WkT_hi,
            nullptr, kp_hi, nullptr, N_, D_, D_, H_, H_, sND, sDD, sND, 1.0f, bk, D_);
        hgemm_kernel<3, false, 2><<<grid, 256, SHM_2P>>>(qc_hi, qc_lo, WqT_hi,
            nullptr, qp_hi, nullptr, M_, D_, D_, H_, H_, sND, sDD, sND, 1.0f, bq, D_);
        hgemm_kernel<2, false, 2><<<grid, 256, SHM_2P>>>(vc_hi, vc_lo, WvT_hi,
            nullptr, vT_hi, nullptr, N_, D_, D_, H_, H_, sND, sDD, sND, 1.0f, bv, D_);
    }

    // 2) scores = (q' @ k'^T) / sqrt(D)   (1-pass)
    {
        dim3 grid(N_ / 256, M_ / 128, BH_);
        const float scale = 0.044194173824159216f;
        hgemm_kernel<0, false, 1><<<grid, 256, SHM_1P>>>(qp_hi, nullptr, kp_hi,
            sc, nullptr, nullptr, M_, N_, D_, 1, BH_, sMD, sND, sMN, scale, nullptr, 0);
    }

    // 3) softmax -> P hi
    softmax_kernel<<<BH_ * M_, 256>>>(sc, P_hi);

    // 4) attn = P @ v'   (1-pass) -> fp16 hi/lo pair, layout [z][m][d]
    {
        dim3 grid(D_ / 256, M_ / 128, BH_);
        hgemm_kernel<1, false, 1><<<grid, 256, SHM_1P>>>(P_hi, nullptr, vT_hi,
            nullptr, at_hi, at_lo, M_, D_, N_, 1, BH_, sMN, sND, sMD, 1.0f, nullptr, 0);
    }

    // 5) out = attn(gathered, k = h*512+d) @ WoP + bo   (2-pass)
    {
        dim3 grid(D_ / 256, M_ / 128, B_);
        hgemm_kernel<0, true, 2><<<grid, 256, SHM_2P>>>(at_hi, at_lo, WoP_hi,
            out, nullptr, nullptr, M_, D_, HD_, 1, 1, sAB, 0, sMD, 1.0f, bo, 0);
    }
}

// round 15
// speedup vs baseline: 7.5747x; 1.2846x over previous
#include <cuda_runtime.h>
#include <cuda_fp16.h>
#include <cstdint>

#define B_  8
#define N_  2048
#define M_  2048
#define D_  512
#define H_  8
#define BH_ (B_ * H_)
#define HD_ (H_ * D_)

// -------------------------------------------------------------------------
// Device scratch — all GEMM operands fp16 hi-only (1-pass scheme).
// -------------------------------------------------------------------------
__device__ __half g_kc_hi[(size_t)B_ * N_ * D_];
__device__ __half g_vc_hi[(size_t)B_ * N_ * D_];
__device__ __half g_qc_hi[(size_t)B_ * M_ * D_];
__device__ __half g_WkT_hi[(size_t)H_ * D_ * D_];
__device__ __half g_WvT_hi[(size_t)H_ * D_ * D_];
__device__ __half g_WqT_hi[(size_t)H_ * D_ * D_];
__device__ __half g_WoP_hi[(size_t)D_ * HD_];        // [n=512][k=h*512+d]
__device__ __half g_kp_hi[(size_t)BH_ * N_ * D_];    // k'
__device__ __half g_qp_hi[(size_t)BH_ * M_ * D_];    // q'
__device__ __half g_vT_hi[(size_t)BH_ * D_ * N_];    // v'^T
__device__ float  g_scores[(size_t)BH_ * M_ * N_];
__device__ __half g_P_hi[(size_t)BH_ * M_ * N_];     // softmax probs
__device__ __half g_at_hi[(size_t)BH_ * M_ * D_];    // attn out [z][m][d]

// -------------------------------------------------------------------------
// PTX helpers (family-baseline instructions only)
// -------------------------------------------------------------------------
__device__ __forceinline__ uint32_t smem_to_u32(const void* p) {
    uint32_t a;
    asm("{ .reg .u64 t; cvta.to.shared.u64 t, %1; cvt.u32.u64 %0, t; }" : "=r"(a) : "l"(p));
    return a;
}
__device__ __forceinline__ void cp16(uint32_t dst, const void* src) {
    asm volatile("cp.async.cg.shared.global [%0], [%1], 16;" :: "r"(dst), "l"(src));
}
#define CP_COMMIT() asm volatile("cp.async.commit_group;" ::: "memory")
#define CP_WAIT2()  asm volatile("cp.async.wait_group 2;" ::: "memory")

__device__ __forceinline__ void ldsm4(uint32_t* r, uint32_t addr) {
    asm volatile("ldmatrix.sync.aligned.m8n8.x4.shared.b16 {%0,%1,%2,%3}, [%4];"
                 : "=r"(r[0]), "=r"(r[1]), "=r"(r[2]), "=r"(r[3]) : "r"(addr));
}
__device__ __forceinline__ void mma16816(float* c, const uint32_t* a,
                                         uint32_t b0, uint32_t b1) {
    asm volatile("mma.sync.aligned.m16n8k16.row.col.f32.f16.f16.f32 "
                 "{%0,%1,%2,%3}, {%4,%5,%6,%7}, {%8,%9}, {%0,%1,%2,%3};"
                 : "+f"(c[0]), "+f"(c[1]), "+f"(c[2]), "+f"(c[3])
                 : "r"(a[0]), "r"(a[1]), "r"(a[2]), "r"(a[3]), "r"(b0), "r"(b1));
}

// -------------------------------------------------------------------------
// 1-pass fp16 tensor-core GEMM.  C[z] = alpha * A[z] @ B[z]^T (+ bias)
// A: [Md, Kd] fp16 row-major.  B: [Nd, Kd] fp16 K-major.
// EPI: 0 = fp32 out; 2 = fp16 transposed out (C[n*Md+m]); 3 = fp16 row-major.
// GA:  gather A from attention layout [h][m][d], k = h*512 + d.
// CTA tile 128(M) x 256(N), BK=64, 256 threads (2x4 warps), warp tile 64x64.
// 4-stage cp.async ring, lookahead 3, ONE __syncthreads per iteration
// (write target (it+3)&3 was last read at it-1; every warp passed the
//  top-of-iter-it barrier after those reads, so no second barrier needed).
// Stage = A(16K) + B(32K) = 48KB; 4 stages = 192KB.
// -------------------------------------------------------------------------
#define STAGE_BYTES 49152u
#define SHM_TOTAL   (4 * 49152)

template <int EPI, bool GA>
__global__ void __launch_bounds__(256, 1) hgemm_kernel(
    const __half* __restrict__ Ah, const __half* __restrict__ Bh,
    float* __restrict__ Cf, __half* __restrict__ Ch,
    int Md, int Nd, int Kd, int divA, int modB,
    long long strideA, long long strideB, long long strideC,
    float alpha, const float* __restrict__ bias, int biasStride)
{
    extern __shared__ char smem[];
    const uint32_t sm0 = smem_to_u32(smem);
    const int tid = threadIdx.x;
    const int wid = tid >> 5, lane = tid & 31;
    const int wm = wid >> 2, wn = wid & 3;           // 2(M) x 4(N) warp grid

    const int z = blockIdx.z;
    Ah += (long long)(z / divA) * strideA;
    Bh += (long long)(z % modB) * strideB;
    const long long coff = (long long)z * strideC;
    const float* bptr = bias ? (bias + (long long)(z % modB) * biasStride) : nullptr;
    const int m0 = blockIdx.y * 128;
    const int n0 = blockIdx.x * 256;

    const int nIter = Kd >> 6;

    auto issue = [&](int it, int st) {
        const uint32_t sb = sm0 + st * STAGE_BYTES;
        const int kb = it * 64;
        const long long ga_off = GA ? ((long long)(kb >> 9) * ((long long)M_ * D_) + (kb & 511))
                                    : 0;
        #pragma unroll
        for (int i = 0; i < 4; i++) {
            int ci = tid + i * 256;          // 0..1023
            int row = ci >> 3;               // 0..127
            int kc8 = ci & 7;
            uint32_t doff = row * 128 + ((kc8 * 16) ^ ((row & 7) << 4));
            const __half* sa;
            if (GA) sa = Ah + ga_off + (long long)(m0 + row) * D_ + kc8 * 8;
            else    sa = Ah + (long long)(m0 + row) * Kd + kb + kc8 * 8;
            cp16(sb + doff, sa);
        }
        #pragma unroll
        for (int i = 0; i < 8; i++) {
            int ci = tid + i * 256;          // 0..2047
            int row = ci >> 3;               // 0..255
            int kc8 = ci & 7;
            uint32_t doff = row * 128 + ((kc8 * 16) ^ ((row & 7) << 4));
            cp16(sb + 16384 + doff, Bh + (long long)(n0 + row) * Kd + kb + kc8 * 8);
        }
    };

    float acc[4][8][4];
    #pragma unroll
    for (int i = 0; i < 4; i++)
        #pragma unroll
        for (int j = 0; j < 8; j++)
            #pragma unroll
            for (int r = 0; r < 4; r++) acc[i][j][r] = 0.0f;

    issue(0, 0); CP_COMMIT();
    issue(1, 1); CP_COMMIT();
    issue(2, 2); CP_COMMIT();

    const int arow_l = wm * 64 + (lane & 15);
    const int akch   = (lane >> 4) << 4;
    const int brow_l = wn * 64 + ((lane >> 4) << 3) + (lane & 7);
    const int bkch   = ((lane >> 3) & 1) << 4;

    for (int it = 0; it < nIter; it++) {
        const int st = it & 3;
        CP_WAIT2();
        __syncthreads();

        const uint32_t sb = sm0 + st * STAGE_BYTES;
        #pragma unroll
        for (int kc = 0; kc < 4; kc++) {
            uint32_t ah[4][4], bh[4][4];
            #pragma unroll
            for (int mf = 0; mf < 4; mf++) {
                int row = arow_l + mf * 16;
                uint32_t addr = sb + row * 128 + ((kc * 32 + akch) ^ ((row & 7) << 4));
                ldsm4(ah[mf], addr);
            }
            #pragma unroll
            for (int ng = 0; ng < 4; ng++) {
                int row = brow_l + ng * 16;
                uint32_t addr = sb + 16384 + row * 128 +
                                ((kc * 32 + bkch) ^ ((row & 7) << 4));
                ldsm4(bh[ng], addr);
            }
            #pragma unroll
            for (int mf = 0; mf < 4; mf++)
                #pragma unroll
                for (int nf = 0; nf < 8; nf++) {
                    const int ng = nf >> 1, j = nf & 1;
                    mma16816(acc[mf][nf], ah[mf], bh[ng][2 * j], bh[ng][2 * j + 1]);
                }
        }
        // no second barrier: write target (it+3)&3 differs from every stage
        // currently being read, and all warps passed this iter's barrier.
        if (it + 3 < nIter) issue(it + 3, (it + 3) & 3);
        CP_COMMIT();
    }

    // ---- epilogue ----
    const int g   = lane >> 2;
    const int cp2 = (lane & 3) * 2;
    #pragma unroll
    for (int mf = 0; mf < 4; mf++) {
        #pragma unroll
        for (int nf = 0; nf < 8; nf++) {
            int row0 = m0 + wm * 64 + mf * 16 + g;
            int row1 = row0 + 8;
            int col  = n0 + wn * 64 + nf * 8 + cp2;
            float v00 = acc[mf][nf][0] * alpha;
            float v01 = acc[mf][nf][1] * alpha;
            float v10 = acc[mf][nf][2] * alpha;
            float v11 = acc[mf][nf][3] * alpha;
            if (bptr) {
                float b0 = bptr[col], b1 = bptr[col + 1];
                v00 += b0; v01 += b1; v10 += b0; v11 += b1;
            }
            if (EPI == 0) {
                *reinterpret_cast<float2*>(Cf + coff + (long long)row0 * Nd + col) =
                    make_float2(v00, v01);
                *reinterpret_cast<float2*>(Cf + coff + (long long)row1 * Nd + col) =
                    make_float2(v10, v11);
            } else if (EPI == 2) {
                Ch[coff + (long long)col * Md + row0]       = __float2half_rn(v00);
                Ch[coff + (long long)(col + 1) * Md + row0] = __float2half_rn(v01);
                Ch[coff + (long long)col * Md + row1]       = __float2half_rn(v10);
                Ch[coff + (long long)(col + 1) * Md + row1] = __float2half_rn(v11);
            } else {  // EPI == 3: fp16 row-major
                __half2 hh0; hh0.x = __float2half_rn(v00); hh0.y = __float2half_rn(v01);
                __half2 hh1; hh1.x = __float2half_rn(v10); hh1.y = __float2half_rn(v11);
                *reinterpret_cast<__half2*>(Ch + coff + (long long)row0 * Nd + col) = hh0;
                *reinterpret_cast<__half2*>(Ch + coff + (long long)row1 * Nd + col) = hh1;
            }
        }
    }
}

// -------------------------------------------------------------------------
// fp32 -> fp16 convert (elementwise, hi only)
// -------------------------------------------------------------------------
__global__ void __launch_bounds__(256) convert_h_kernel(
    const float* __restrict__ src, __half* __restrict__ hi, size_t n4)
{
    size_t i = (size_t)blockIdx.x * 256 + threadIdx.x;
    if (i >= n4) return;
    float4 v = reinterpret_cast<const float4*>(src)[i];
    __half2 ha; ha.x = __float2half_rn(v.x); ha.y = __float2half_rn(v.y);
    __half2 hb; hb.x = __float2half_rn(v.z); hb.y = __float2half_rn(v.w);
    reinterpret_cast<__half2*>(hi)[2 * i]     = ha;
    reinterpret_cast<__half2*>(hi)[2 * i + 1] = hb;
}

// -------------------------------------------------------------------------
// Batched transpose: dst[z][c][r] = fp16(src[z][r][c])
// -------------------------------------------------------------------------
__global__ void __launch_bounds__(256) transpose_h_kernel(
    const float* __restrict__ src, __half* __restrict__ hi, int R, int C)
{
    __shared__ float t[32][33];
    const size_t zoff = (size_t)blockIdx.z * R * C;
    int tx = threadIdx.x, ty = threadIdx.y;
    int x = blockIdx.x * 32 + tx;
    int y = blockIdx.y * 32 + ty;
    #pragma unroll
    for (int j = 0; j < 32; j += 8)
        t[ty + j][tx] = src[zoff + (size_t)(y + j) * C + x];
    __syncthreads();
    int x2 = blockIdx.y * 32 + tx;
    int y2 = blockIdx.x * 32 + ty;
    #pragma unroll
    for (int j = 0; j < 32; j += 8)
        hi[zoff + (size_t)(y2 + j) * R + x2] = __float2half_rn(t[tx][ty + j]);
}

// -------------------------------------------------------------------------
// Wo permute+transpose: out[n][k = h*512+d] = fp16(Wo[d*8+h][n])
// -------------------------------------------------------------------------
__global__ void __launch_bounds__(256) wo_permute_h_kernel(
    const float* __restrict__ Wo, __half* __restrict__ hi)
{
    __shared__ float t[32][33];
    int tx = threadIdx.x, ty = threadIdx.y;       // 32 x 8
    int kb = blockIdx.x * 32;
    int nb = blockIdx.y * 32;
    int h  = kb >> 9;
    int d0 = kb & 511;
    #pragma unroll
    for (int j = 0; j < 32; j += 8) {
        int d = d0 + ty + j;
        t[ty + j][tx] = Wo[(size_t)(d * 8 + h) * D_ + nb + tx];
    }
    __syncthreads();
    #pragma unroll
    for (int j = 0; j < 32; j += 8) {
        int n = nb + ty + j;
        hi[(size_t)n * HD_ + kb + tx] = __float2half_rn(t[tx][ty + j]);
    }
}

// -------------------------------------------------------------------------
// Row softmax over N_=2048, emits fp16 probability array.
// -------------------------------------------------------------------------
__global__ void __launch_bounds__(256) softmax_kernel(
    const float* __restrict__ S, __half* __restrict__ Ph)
{
    const long long roff = (long long)blockIdx.x * N_;
    const float* p = S + roff;
    const int tid = threadIdx.x;

    float4 v0 = *reinterpret_cast<const float4*>(p + tid * 8);
    float4 v1 = *reinterpret_cast<const float4*>(p + tid * 8 + 4);

    float m = fmaxf(fmaxf(fmaxf(v0.x, v0.y), fmaxf(v0.z, v0.w)),
                    fmaxf(fmaxf(v1.x, v1.y), fmaxf(v1.z, v1.w)));
    #pragma unroll
    for (int o = 16; o > 0; o >>= 1)
        m = fmaxf(m, __shfl_xor_sync(0xffffffffu, m, o));

    __shared__ float smax[8];
    __shared__ float ssum[8];
    if ((tid & 31) == 0) smax[tid >> 5] = m;
    __syncthreads();
    m = smax[0];
    #pragma unroll
    for (int i = 1; i < 8; i++) m = fmaxf(m, smax[i]);

    v0.x = __expf(v0.x - m); v0.y = __expf(v0.y - m);
    v0.z = __expf(v0.z - m); v0.w = __expf(v0.w - m);
    v1.x = __expf(v1.x - m); v1.y = __expf(v1.y - m);
    v1.z = __expf(v1.z - m); v1.w = __expf(v1.w - m);

    float s = v0.x + v0.y + v0.z + v0.w + v1.x + v1.y + v1.z + v1.w;
    #pragma unroll
    for (int o = 16; o > 0; o >>= 1)
        s += __shfl_xor_sync(0xffffffffu, s, o);
    if ((tid & 31) == 0) ssum[tid >> 5] = s;
    __syncthreads();
    s = 0.0f;
    #pragma unroll
    for (int i = 0; i < 8; i++) s += ssum[i];

    const float inv = 1.0f / s;
    __half2 hh[4];
    hh[0].x = __float2half_rn(v0.x * inv); hh[0].y = __float2half_rn(v0.y * inv);
    hh[1].x = __float2half_rn(v0.z * inv); hh[1].y = __float2half_rn(v0.w * inv);
    hh[2].x = __float2half_rn(v1.x * inv); hh[2].y = __float2half_rn(v1.y * inv);
    hh[3].x = __float2half_rn(v1.z * inv); hh[3].y = __float2half_rn(v1.w * inv);
    *reinterpret_cast<uint4*>(Ph + roff + tid * 8) = *reinterpret_cast<uint4*>(hh);
}

// -------------------------------------------------------------------------
// Launch
// -------------------------------------------------------------------------
extern "C" void kernel_launch(void* const* d_in, const int* in_sizes, int n_in,
                              void* d_out, int out_size)
{
    (void)in_sizes; (void)n_in; (void)out_size;
    const float* k  = (const float*)d_in[0];
    const float* v  = (const float*)d_in[1];
    const float* q  = (const float*)d_in[2];
    const float* Wk = (const float*)d_in[3];
    const float* bk = (const float*)d_in[4];
    const float* Wv = (const float*)d_in[5];
    const float* bv = (const float*)d_in[6];
    const float* Wq = (const float*)d_in[7];
    const float* bq = (const float*)d_in[8];
    const float* Wo = (const float*)d_in[9];
    const float* bo = (const float*)d_in[10];
    float* out = (float*)d_out;

    __half *kc_hi, *vc_hi, *qc_hi;
    __half *WkT_hi, *WvT_hi, *WqT_hi, *WoP_hi;
    __half *kp_hi, *qp_hi, *vT_hi, *P_hi, *at_hi;
    float *sc;
    cudaGetSymbolAddress((void**)&kc_hi, g_kc_hi);
    cudaGetSymbolAddress((void**)&vc_hi, g_vc_hi);
    cudaGetSymbolAddress((void**)&qc_hi, g_qc_hi);
    cudaGetSymbolAddress((void**)&WkT_hi, g_WkT_hi);
    cudaGetSymbolAddress((void**)&WvT_hi, g_WvT_hi);
    cudaGetSymbolAddress((void**)&WqT_hi, g_WqT_hi);
    cudaGetSymbolAddress((void**)&WoP_hi, g_WoP_hi);
    cudaGetSymbolAddress((void**)&kp_hi, g_kp_hi);
    cudaGetSymbolAddress((void**)&qp_hi, g_qp_hi);
    cudaGetSymbolAddress((void**)&vT_hi, g_vT_hi);
    cudaGetSymbolAddress((void**)&P_hi, g_P_hi);
    cudaGetSymbolAddress((void**)&at_hi, g_at_hi);
    cudaGetSymbolAddress((void**)&sc, g_scores);

    const long long sND = (long long)N_ * D_;
    const long long sDD = (long long)D_ * D_;
    const long long sMN = (long long)M_ * N_;
    const long long sMD = (long long)M_ * D_;
    const long long sAB = (long long)H_ * M_ * D_;   // attn batch stride

    cudaFuncSetAttribute(hgemm_kernel<0, false>, cudaFuncAttributeMaxDynamicSharedMemorySize, SHM_TOTAL);
    cudaFuncSetAttribute(hgemm_kernel<2, false>, cudaFuncAttributeMaxDynamicSharedMemorySize, SHM_TOTAL);
    cudaFuncSetAttribute(hgemm_kernel<3, false>, cudaFuncAttributeMaxDynamicSharedMemorySize, SHM_TOTAL);
    cudaFuncSetAttribute(hgemm_kernel<0, true>,  cudaFuncAttributeMaxDynamicSharedMemorySize, SHM_TOTAL);

    // 0) convert inputs + weights to fp16
    {
        size_t n4 = (size_t)B_ * N_ * D_ / 4;
        int gb = (int)((n4 + 255) / 256);
        convert_h_kernel<<<gb, 256>>>(k, kc_hi, n4);
        convert_h_kernel<<<gb, 256>>>(v, vc_hi, n4);
        convert_h_kernel<<<gb, 256>>>(q, qc_hi, n4);
        dim3 tb(32, 8);
        transpose_h_kernel<<<dim3(D_ / 32, D_ / 32, H_), tb>>>(Wk, WkT_hi, D_, D_);
        transpose_h_kernel<<<dim3(D_ / 32, D_ / 32, H_), tb>>>(Wv, WvT_hi, D_, D_);
        transpose_h_kernel<<<dim3(D_ / 32, D_ / 32, H_), tb>>>(Wq, WqT_hi, D_, D_);
        wo_permute_h_kernel<<<dim3(HD_ / 32, D_ / 32), tb>>>(Wo, WoP_hi);
    }

    // 1) projections (1-pass)
    {
        dim3 grid(D_ / 256, N_ / 128, BH_);
        hgemm_kernel<3, false><<<grid, 256, SHM_TOTAL>>>(kc_hi, WkT_hi,
            nullptr, kp_hi, N_, D_, D_, H_, H_, sND, sDD, sND, 1.0f, bk, D_);
        hgemm_kernel<3, false><<<grid, 256, SHM_TOTAL>>>(qc_hi, WqT_hi,
            nullptr, qp_hi, M_, D_, D_, H_, H_, sND, sDD, sND, 1.0f, bq, D_);
        hgemm_kernel<2, false><<<grid, 256, SHM_TOTAL>>>(vc_hi, WvT_hi,
            nullptr, vT_hi, N_, D_, D_, H_, H_, sND, sDD, sND, 1.0f, bv, D_);
    }

    // 2) scores = (q' @ k'^T) / sqrt(D)
    {
        dim3 grid(N_ / 256, M_ / 128, BH_);
        const float scale = 0.044194173824159216f;
        hgemm_kernel<0, false><<<grid, 256, SHM_TOTAL>>>(qp_hi, kp_hi,
            sc, nullptr, M_, N_, D_, 1, BH_, sMD, sND, sMN, scale, nullptr, 0);
    }

    // 3) softmax -> P
    softmax_kernel<<<BH_ * M_, 256>>>(sc, P_hi);

    // 4) attn = P @ v'  -> fp16, layout [z][m][d]
    {
        dim3 grid(D_ / 256, M_ / 128, BH_);
        hgemm_kernel<3, false><<<grid, 256, SHM_TOTAL>>>(P_hi, vT_hi,
            nullptr, at_hi, M_, D_, N_, 1, BH_, sMN, sND, sMD, 1.0f, nullptr, 0);
    }

    // 5) out = attn(gathered, k = h*512+d) @ WoP + bo
    {
        dim3 grid(D_ / 256, M_ / 128, B_);
        hgemm_kernel<0, true><<<grid, 256, SHM_TOTAL>>>(at_hi, WoP_hi,
            out, nullptr, M_, D_, HD_, 1, 1, sAB, 0, sMD, 1.0f, bo, 0);
    }
}